// round 1
// baseline (speedup 1.0000x reference)
#include <cuda_runtime.h>
#include <cuda_bf16.h>

// Problem dims
#define BB   16
#define NNN  32
#define SS   128
#define DD   512
#define HH   8
#define DKV  64
#define NTOK (BB*NNN*SS)          // 65536 tokens
#define YSIZE  (NTOK*DD)          // 33554432
#define ATTNSZ (BB*NNN*HH*SS*SS)  // 67108864

// ---------------- scratch (no cudaMalloc allowed) ----------------
__device__ float g_Qp[NTOK * DD];
__device__ float g_Kp[NTOK * DD];
__device__ float g_Vp[NTOK * DD];
__device__ float g_res[NTOK * DD];
__device__ float g_outp[NTOK * DD];
__device__ int   g_mask_kind;   // 0=int32, 1=float32, 2=uint8

// ---------------- mask dtype detection ----------------
__global__ void detect_mask_kernel(const unsigned int* __restrict__ mw, int nwords) {
    __shared__ int s_not01, s_isfloat;
    if (threadIdx.x == 0) { s_not01 = 0; s_isfloat = 0; }
    __syncthreads();
    for (int i = threadIdx.x; i < nwords; i += blockDim.x) {
        unsigned v = mw[i];
        if (v == 0x3f800000u) s_isfloat = 1;
        else if (v > 1u) s_not01 = 1;
    }
    __syncthreads();
    if (threadIdx.x == 0) {
        g_mask_kind = s_not01 ? 2 : (s_isfloat ? 1 : 0);
    }
}

// ---------------- SGEMM: C[m][n] = sum_k A[m*K+k] * B[n*K+k] ----------------
// BM=BN=128, BK=8, 256 threads, 8x8 register tile.
__global__ __launch_bounds__(256) void sgemm_tn(
    const float* __restrict__ A, const float* __restrict__ B, float* __restrict__ C,
    int M, int N, int K)
{
    __shared__ float As[8][128];
    __shared__ float Bs[8][128];
    int t  = threadIdx.x;
    int m0 = blockIdx.x * 128;
    int n0 = blockIdx.y * 128;
    int tx = t & 15, ty = t >> 4;
    int rm = ty * 8, rn = tx * 8;
    float acc[8][8] = {};
    int lRow = t >> 1;         // 0..127
    int lCol = (t & 1) * 4;    // 0 or 4

    for (int k0 = 0; k0 < K; k0 += 8) {
        float4 av = *(const float4*)&A[(size_t)(m0 + lRow) * K + k0 + lCol];
        float4 bv = *(const float4*)&B[(size_t)(n0 + lRow) * K + k0 + lCol];
        As[lCol + 0][lRow] = av.x; As[lCol + 1][lRow] = av.y;
        As[lCol + 2][lRow] = av.z; As[lCol + 3][lRow] = av.w;
        Bs[lCol + 0][lRow] = bv.x; Bs[lCol + 1][lRow] = bv.y;
        Bs[lCol + 2][lRow] = bv.z; Bs[lCol + 3][lRow] = bv.w;
        __syncthreads();
#pragma unroll
        for (int kk = 0; kk < 8; kk++) {
            float4 a0 = *(const float4*)&As[kk][rm];
            float4 a1 = *(const float4*)&As[kk][rm + 4];
            float4 b0 = *(const float4*)&Bs[kk][rn];
            float4 b1 = *(const float4*)&Bs[kk][rn + 4];
            float a[8] = {a0.x, a0.y, a0.z, a0.w, a1.x, a1.y, a1.z, a1.w};
            float b[8] = {b0.x, b0.y, b0.z, b0.w, b1.x, b1.y, b1.z, b1.w};
#pragma unroll
            for (int i = 0; i < 8; i++)
#pragma unroll
                for (int j = 0; j < 8; j++)
                    acc[i][j] += a[i] * b[j];
        }
        __syncthreads();
    }
#pragma unroll
    for (int i = 0; i < 8; i++) {
        float4 c0 = make_float4(acc[i][0], acc[i][1], acc[i][2], acc[i][3]);
        float4 c1 = make_float4(acc[i][4], acc[i][5], acc[i][6], acc[i][7]);
        size_t off = (size_t)(m0 + rm + i) * N + n0 + rn;
        *(float4*)&C[off]     = c0;
        *(float4*)&C[off + 4] = c1;
    }
}

// ---------------- fused attention per (bn, h) ----------------
// smem: Qt[64][128], Kt[64][128] (transposed), Vs[128][64], P[128][129]
#define PSTR 129
#define ATTN_SMEM ((64*128 + 64*128 + 128*64 + 128*PSTR) * 4)

__global__ __launch_bounds__(256) void attn_kernel(
    const float* __restrict__ Qp, const float* __restrict__ Kp, const float* __restrict__ Vp,
    const void* __restrict__ mask, float* __restrict__ attn_out, float* __restrict__ res)
{
    extern __shared__ float sm[];
    float* Qt = sm;
    float* Kt = Qt + 64 * 128;
    float* Vs = Kt + 64 * 128;
    float* P  = Vs + 128 * 64;

    int bn = blockIdx.x >> 3;
    int h  = blockIdx.x & 7;
    int t  = threadIdx.x;

    const size_t baseQ = ((size_t)bn * SS) * DD + (size_t)h * DKV;

    // load tiles: Q,K transposed into [k][r]; V direct [r][k]
    for (int i = t; i < 128 * 16; i += 256) {
        int r  = i >> 4;
        int k4 = (i & 15) << 2;
        float4 q = *(const float4*)&Qp[baseQ + (size_t)r * DD + k4];
        float4 k = *(const float4*)&Kp[baseQ + (size_t)r * DD + k4];
        float4 v = *(const float4*)&Vp[baseQ + (size_t)r * DD + k4];
        Qt[(k4 + 0) * 128 + r] = q.x; Qt[(k4 + 1) * 128 + r] = q.y;
        Qt[(k4 + 2) * 128 + r] = q.z; Qt[(k4 + 3) * 128 + r] = q.w;
        Kt[(k4 + 0) * 128 + r] = k.x; Kt[(k4 + 1) * 128 + r] = k.y;
        Kt[(k4 + 2) * 128 + r] = k.z; Kt[(k4 + 3) * 128 + r] = k.w;
        *(float4*)&Vs[r * 64 + k4] = v;
    }
    __syncthreads();

    // scores: 16x16 threads, 8x8 tiles
    int tx = t & 15, ty = t >> 4;
    int r0 = ty * 8, c0 = tx * 8;
    {
        float acc[8][8] = {};
#pragma unroll 4
        for (int k = 0; k < 64; k++) {
            float4 a0 = *(const float4*)&Qt[k * 128 + r0];
            float4 a1 = *(const float4*)&Qt[k * 128 + r0 + 4];
            float4 b0 = *(const float4*)&Kt[k * 128 + c0];
            float4 b1 = *(const float4*)&Kt[k * 128 + c0 + 4];
            float a[8] = {a0.x, a0.y, a0.z, a0.w, a1.x, a1.y, a1.z, a1.w};
            float b[8] = {b0.x, b0.y, b0.z, b0.w, b1.x, b1.y, b1.z, b1.w};
#pragma unroll
            for (int i = 0; i < 8; i++)
#pragma unroll
                for (int j = 0; j < 8; j++)
                    acc[i][j] += a[i] * b[j];
        }
#pragma unroll
        for (int i = 0; i < 8; i++)
#pragma unroll
            for (int j = 0; j < 8; j++)
                P[(r0 + i) * PSTR + c0 + j] = acc[i][j] * 0.125f;
    }
    __syncthreads();

    // mask + softmax (one thread per row)
    int kind = g_mask_kind;
    if (t < 128) {
        int r = t;
        size_t mbase = ((size_t)bn * SS + r) * SS;
        float mx = -3.4e38f;
        for (int c = 0; c < 128; c++) {
            bool vis;
            if (kind == 2)      vis = ((const unsigned char*)mask)[mbase + c] != 0;
            else if (kind == 1) vis = ((const float*)mask)[mbase + c] != 0.0f;
            else                vis = ((const int*)mask)[mbase + c] != 0;
            float s = vis ? P[r * PSTR + c] : -1e9f;
            P[r * PSTR + c] = s;
            mx = fmaxf(mx, s);
        }
        float sum = 0.0f;
        for (int c = 0; c < 128; c++) {
            float e = __expf(P[r * PSTR + c] - mx);
            P[r * PSTR + c] = e;
            sum += e;
        }
        float inv = 1.0f / sum;
        for (int c = 0; c < 128; c++)
            P[r * PSTR + c] *= inv;
    }
    __syncthreads();

    // coalesced attn output write: layout [bn, h, r, c] = blockIdx.x * 16384 + r*128 + c
    {
        float* aout = attn_out + (size_t)blockIdx.x * (SS * SS);
        for (int i = t; i < SS * SS; i += 256) {
            int r = i >> 7, c = i & 127;
            aout[i] = P[r * PSTR + c];
        }
    }

    // O = P @ V : each thread 8 rows x 4 cols
    {
        int cv = tx * 4;
        float po[8][4] = {};
#pragma unroll 4
        for (int tt = 0; tt < 128; tt++) {
            float a[8];
#pragma unroll
            for (int i = 0; i < 8; i++) a[i] = P[(r0 + i) * PSTR + tt];
            float4 b = *(const float4*)&Vs[tt * 64 + cv];
#pragma unroll
            for (int i = 0; i < 8; i++) {
                po[i][0] += a[i] * b.x;
                po[i][1] += a[i] * b.y;
                po[i][2] += a[i] * b.z;
                po[i][3] += a[i] * b.w;
            }
        }
#pragma unroll
        for (int i = 0; i < 8; i++) {
            float4 o = make_float4(po[i][0], po[i][1], po[i][2], po[i][3]);
            *(float4*)&res[((size_t)bn * SS + r0 + i) * DD + h * DKV + cv] = o;
        }
    }
}

// ---------------- residual + LayerNorm ----------------
__global__ __launch_bounds__(256) void ln_kernel(
    const float* __restrict__ O, const float* __restrict__ X,
    const float* __restrict__ gamma, const float* __restrict__ beta,
    float* __restrict__ Y)
{
    __shared__ float red[256];
    size_t base = (size_t)blockIdx.x * DD;
    int t = threadIdx.x;
    float x0 = O[base + t]       + X[base + t];
    float x1 = O[base + t + 256] + X[base + t + 256];

    red[t] = x0 + x1;
    __syncthreads();
    for (int o = 128; o > 0; o >>= 1) {
        if (t < o) red[t] += red[t + o];
        __syncthreads();
    }
    float mean = red[0] * (1.0f / DD);
    __syncthreads();

    float d0 = x0 - mean, d1 = x1 - mean;
    red[t] = d0 * d0 + d1 * d1;
    __syncthreads();
    for (int o = 128; o > 0; o >>= 1) {
        if (t < o) red[t] += red[t + o];
        __syncthreads();
    }
    float var = red[0] * (1.0f / DD);
    float inv = rsqrtf(var + 1e-5f);

    Y[base + t]       = d0 * inv * gamma[t]       + beta[t];
    Y[base + t + 256] = d1 * inv * gamma[t + 256] + beta[t + 256];
}

// ---------------- launch ----------------
extern "C" void kernel_launch(void* const* d_in, const int* in_sizes, int n_in,
                              void* d_out, int out_size)
{
    const float* Q     = (const float*)d_in[0];
    const float* K     = (const float*)d_in[1];
    const float* V     = (const float*)d_in[2];
    const void*  mask  = d_in[3];
    const float* WQ    = (const float*)d_in[4];
    const float* WK    = (const float*)d_in[5];
    const float* WV    = (const float*)d_in[6];
    const float* Wfc   = (const float*)d_in[7];
    const float* gamma = (const float*)d_in[8];
    const float* beta  = (const float*)d_in[9];

    float* y    = (float*)d_out;
    float* attn = y + (size_t)YSIZE;

    cudaFuncSetAttribute(attn_kernel, cudaFuncAttributeMaxDynamicSharedMemorySize, ATTN_SMEM);

    void *pQp, *pKp, *pVp, *pRes, *pOutp;
    cudaGetSymbolAddress(&pQp,  g_Qp);
    cudaGetSymbolAddress(&pKp,  g_Kp);
    cudaGetSymbolAddress(&pVp,  g_Vp);
    cudaGetSymbolAddress(&pRes, g_res);
    cudaGetSymbolAddress(&pOutp,g_outp);

    detect_mask_kernel<<<1, 256>>>((const unsigned int*)mask, 65536);

    dim3 g(NTOK / 128, DD / 128);  // (512, 4)
    sgemm_tn<<<g, 256>>>(Q, WQ, (float*)pQp, NTOK, DD, DD);
    sgemm_tn<<<g, 256>>>(K, WK, (float*)pKp, NTOK, DD, DD);
    sgemm_tn<<<g, 256>>>(V, WV, (float*)pVp, NTOK, DD, DD);

    attn_kernel<<<BB * NNN * HH, 256, ATTN_SMEM>>>(
        (const float*)pQp, (const float*)pKp, (const float*)pVp, mask, attn, (float*)pRes);

    sgemm_tn<<<g, 256>>>((const float*)pRes, Wfc, (float*)pOutp, NTOK, DD, DD);

    ln_kernel<<<NTOK, 256>>>((const float*)pOutp, Q, gamma, beta, y);
}

// round 2
// speedup vs baseline: 1.7631x; 1.7631x over previous
#include <cuda_runtime.h>
#include <cuda_bf16.h>

// Problem dims
#define BB   16
#define NNN  32
#define SS   128
#define DD   512
#define HH   8
#define DKV  64
#define NTOK (BB*NNN*SS)          // 65536 tokens
#define YSIZE  (NTOK*DD)          // 33554432
#define ATTNSZ (BB*NNN*HH*SS*SS)  // 67108864

// ---------------- scratch (no cudaMalloc allowed) ----------------
__device__ float g_Qp[NTOK * DD];
__device__ float g_Kp[NTOK * DD];
__device__ float g_Vp[NTOK * DD];
__device__ float g_res[NTOK * DD];
__device__ float g_outp[NTOK * DD];
__device__ int   g_mask_kind;   // 0=int32, 1=float32, 2=uint8

// ---------------- mask dtype detection ----------------
__global__ void detect_mask_kernel(const unsigned int* __restrict__ mw, int nwords) {
    __shared__ int s_not01, s_isfloat;
    if (threadIdx.x == 0) { s_not01 = 0; s_isfloat = 0; }
    __syncthreads();
    for (int i = threadIdx.x; i < nwords; i += blockDim.x) {
        unsigned v = mw[i];
        if (v == 0x3f800000u) s_isfloat = 1;
        else if (v > 1u) s_not01 = 1;
    }
    __syncthreads();
    if (threadIdx.x == 0) {
        g_mask_kind = s_not01 ? 2 : (s_isfloat ? 1 : 0);
    }
}

// ---------------- bf16 helpers ----------------
__device__ __forceinline__ unsigned pack_bf16(float lo, float hi) {
    // d = {upper = hi, lower = lo}
    unsigned d;
    asm("cvt.rn.bf16x2.f32 %0, %1, %2;" : "=r"(d) : "f"(hi), "f"(lo));
    return d;
}
__device__ __forceinline__ float bf_lo_f(unsigned p) { return __uint_as_float(p << 16); }
__device__ __forceinline__ float bf_hi_f(unsigned p) { return __uint_as_float(p & 0xFFFF0000u); }

__device__ __forceinline__ void mma16816(float c[4],
    unsigned a0, unsigned a1, unsigned a2, unsigned a3, unsigned b0, unsigned b1)
{
    asm volatile(
        "mma.sync.aligned.m16n8k16.row.col.f32.bf16.bf16.f32 "
        "{%0,%1,%2,%3}, {%4,%5,%6,%7}, {%8,%9}, {%0,%1,%2,%3};"
        : "+f"(c[0]), "+f"(c[1]), "+f"(c[2]), "+f"(c[3])
        : "r"(a0), "r"(a1), "r"(a2), "r"(a3), "r"(b0), "r"(b1));
}

// ---------------- GEMM (bf16x3 split, tensor pipe) ----------------
// C[m][n] = sum_k A[m*K+k] * B[n*K+k]. M mult of 128, N mult of 128, K mult of 32.
#define SMSTR 40   // bf16 elements per smem row (padded from 32)

__global__ __launch_bounds__(256, 2) void gemm_bf16s(
    const float* __restrict__ A, const float* __restrict__ B, float* __restrict__ C,
    int M, int N, int K)
{
    __shared__ __nv_bfloat16 Ahi[128 * SMSTR], Alo[128 * SMSTR];
    __shared__ __nv_bfloat16 Bhi[128 * SMSTR], Blo[128 * SMSTR];

    int tid  = threadIdx.x;
    int lane = tid & 31, wid = tid >> 5;
    int wm = wid & 1, wn = wid >> 1;   // warp tile: 64 (m) x 32 (n)
    int g = lane >> 2, q = lane & 3;
    int m0 = blockIdx.x * 128, n0 = blockIdx.y * 128;

    float acc[4][4][4] = {};

    for (int k0 = 0; k0 < K; k0 += 32) {
        __syncthreads();
        // fill: LDG fp32 -> split hi/lo bf16 -> STS
#pragma unroll
        for (int j = 0; j < 4; j++) {
            int idx = j * 256 + tid;
            int row = idx >> 3, c4 = (idx & 7) << 2;
            float4 av = *(const float4*)&A[(size_t)(m0 + row) * K + k0 + c4];
            float4 bv = *(const float4*)&B[(size_t)(n0 + row) * K + k0 + c4];

            unsigned ah01 = pack_bf16(av.x, av.y);
            unsigned ah23 = pack_bf16(av.z, av.w);
            unsigned al01 = pack_bf16(av.x - bf_lo_f(ah01), av.y - bf_hi_f(ah01));
            unsigned al23 = pack_bf16(av.z - bf_lo_f(ah23), av.w - bf_hi_f(ah23));
            *(uint2*)&Ahi[row * SMSTR + c4] = make_uint2(ah01, ah23);
            *(uint2*)&Alo[row * SMSTR + c4] = make_uint2(al01, al23);

            unsigned bh01 = pack_bf16(bv.x, bv.y);
            unsigned bh23 = pack_bf16(bv.z, bv.w);
            unsigned bl01 = pack_bf16(bv.x - bf_lo_f(bh01), bv.y - bf_hi_f(bh01));
            unsigned bl23 = pack_bf16(bv.z - bf_lo_f(bh23), bv.w - bf_hi_f(bh23));
            *(uint2*)&Bhi[row * SMSTR + c4] = make_uint2(bh01, bh23);
            *(uint2*)&Blo[row * SMSTR + c4] = make_uint2(bl01, bl23);
        }
        __syncthreads();

#pragma unroll
        for (int kb = 0; kb < 32; kb += 16) {
            int kk = kb + 2 * q;
            // A fragments (hi 0..3, lo 4..7) for 4 m-tiles
            unsigned af[4][8];
#pragma unroll
            for (int i = 0; i < 4; i++) {
                int r0 = wm * 64 + i * 16 + g;
                af[i][0] = *(const unsigned*)&Ahi[r0 * SMSTR + kk];
                af[i][1] = *(const unsigned*)&Ahi[(r0 + 8) * SMSTR + kk];
                af[i][2] = *(const unsigned*)&Ahi[r0 * SMSTR + kk + 8];
                af[i][3] = *(const unsigned*)&Ahi[(r0 + 8) * SMSTR + kk + 8];
                af[i][4] = *(const unsigned*)&Alo[r0 * SMSTR + kk];
                af[i][5] = *(const unsigned*)&Alo[(r0 + 8) * SMSTR + kk];
                af[i][6] = *(const unsigned*)&Alo[r0 * SMSTR + kk + 8];
                af[i][7] = *(const unsigned*)&Alo[(r0 + 8) * SMSTR + kk + 8];
            }
#pragma unroll
            for (int j = 0; j < 4; j++) {
                int nr = wn * 32 + j * 8 + g;
                unsigned bh0 = *(const unsigned*)&Bhi[nr * SMSTR + kk];
                unsigned bh1 = *(const unsigned*)&Bhi[nr * SMSTR + kk + 8];
                unsigned bl0 = *(const unsigned*)&Blo[nr * SMSTR + kk];
                unsigned bl1 = *(const unsigned*)&Blo[nr * SMSTR + kk + 8];
#pragma unroll
                for (int i = 0; i < 4; i++) {
                    mma16816(acc[i][j], af[i][0], af[i][1], af[i][2], af[i][3], bh0, bh1);
                    mma16816(acc[i][j], af[i][0], af[i][1], af[i][2], af[i][3], bl0, bl1);
                    mma16816(acc[i][j], af[i][4], af[i][5], af[i][6], af[i][7], bh0, bh1);
                }
            }
        }
    }

    // epilogue
#pragma unroll
    for (int i = 0; i < 4; i++) {
#pragma unroll
        for (int j = 0; j < 4; j++) {
            int row = m0 + wm * 64 + i * 16 + g;
            int col = n0 + wn * 32 + j * 8 + 2 * q;
            *(float2*)&C[(size_t)row * N + col]       = make_float2(acc[i][j][0], acc[i][j][1]);
            *(float2*)&C[(size_t)(row + 8) * N + col] = make_float2(acc[i][j][2], acc[i][j][3]);
        }
    }
}

// ---------------- fused attention per (bn, h) ----------------
#define PSTR 129
#define ATTN_SMEM ((64*128 + 64*128 + 128*64 + 128*PSTR) * 4)

__global__ __launch_bounds__(256) void attn_kernel(
    const float* __restrict__ Qp, const float* __restrict__ Kp, const float* __restrict__ Vp,
    const void* __restrict__ mask, float* __restrict__ attn_out, float* __restrict__ res)
{
    extern __shared__ float sm[];
    float* Qt = sm;
    float* Kt = Qt + 64 * 128;
    float* Vs = Kt + 64 * 128;
    float* P  = Vs + 128 * 64;

    int bn = blockIdx.x >> 3;
    int h  = blockIdx.x & 7;
    int t  = threadIdx.x;

    const size_t baseQ = ((size_t)bn * SS) * DD + (size_t)h * DKV;

    for (int i = t; i < 128 * 16; i += 256) {
        int r  = i >> 4;
        int k4 = (i & 15) << 2;
        float4 q = *(const float4*)&Qp[baseQ + (size_t)r * DD + k4];
        float4 k = *(const float4*)&Kp[baseQ + (size_t)r * DD + k4];
        float4 v = *(const float4*)&Vp[baseQ + (size_t)r * DD + k4];
        Qt[(k4 + 0) * 128 + r] = q.x; Qt[(k4 + 1) * 128 + r] = q.y;
        Qt[(k4 + 2) * 128 + r] = q.z; Qt[(k4 + 3) * 128 + r] = q.w;
        Kt[(k4 + 0) * 128 + r] = k.x; Kt[(k4 + 1) * 128 + r] = k.y;
        Kt[(k4 + 2) * 128 + r] = k.z; Kt[(k4 + 3) * 128 + r] = k.w;
        *(float4*)&Vs[r * 64 + k4] = v;
    }
    __syncthreads();

    int tx = t & 15, ty = t >> 4;
    int r0 = ty * 8, c0 = tx * 8;
    {
        float acc[8][8] = {};
#pragma unroll 4
        for (int k = 0; k < 64; k++) {
            float4 a0 = *(const float4*)&Qt[k * 128 + r0];
            float4 a1 = *(const float4*)&Qt[k * 128 + r0 + 4];
            float4 b0 = *(const float4*)&Kt[k * 128 + c0];
            float4 b1 = *(const float4*)&Kt[k * 128 + c0 + 4];
            float a[8] = {a0.x, a0.y, a0.z, a0.w, a1.x, a1.y, a1.z, a1.w};
            float b[8] = {b0.x, b0.y, b0.z, b0.w, b1.x, b1.y, b1.z, b1.w};
#pragma unroll
            for (int i = 0; i < 8; i++)
#pragma unroll
                for (int j = 0; j < 8; j++)
                    acc[i][j] += a[i] * b[j];
        }
#pragma unroll
        for (int i = 0; i < 8; i++)
#pragma unroll
            for (int j = 0; j < 8; j++)
                P[(r0 + i) * PSTR + c0 + j] = acc[i][j] * 0.125f;
    }
    __syncthreads();

    int kind = g_mask_kind;
    if (t < 128) {
        int r = t;
        size_t mbase = ((size_t)bn * SS + r) * SS;
        float mx = -3.4e38f;
        for (int c = 0; c < 128; c++) {
            bool vis;
            if (kind == 2)      vis = ((const unsigned char*)mask)[mbase + c] != 0;
            else if (kind == 1) vis = ((const float*)mask)[mbase + c] != 0.0f;
            else                vis = ((const int*)mask)[mbase + c] != 0;
            float s = vis ? P[r * PSTR + c] : -1e9f;
            P[r * PSTR + c] = s;
            mx = fmaxf(mx, s);
        }
        float sum = 0.0f;
        for (int c = 0; c < 128; c++) {
            float e = __expf(P[r * PSTR + c] - mx);
            P[r * PSTR + c] = e;
            sum += e;
        }
        float inv = 1.0f / sum;
        for (int c = 0; c < 128; c++)
            P[r * PSTR + c] *= inv;
    }
    __syncthreads();

    {
        float* aout = attn_out + (size_t)blockIdx.x * (SS * SS);
        for (int i = t; i < SS * SS; i += 256) {
            int r = i >> 7, c = i & 127;
            aout[i] = P[r * PSTR + c];
        }
    }

    {
        int cv = tx * 4;
        float po[8][4] = {};
#pragma unroll 4
        for (int tt = 0; tt < 128; tt++) {
            float a[8];
#pragma unroll
            for (int i = 0; i < 8; i++) a[i] = P[(r0 + i) * PSTR + tt];
            float4 b = *(const float4*)&Vs[tt * 64 + cv];
#pragma unroll
            for (int i = 0; i < 8; i++) {
                po[i][0] += a[i] * b.x;
                po[i][1] += a[i] * b.y;
                po[i][2] += a[i] * b.z;
                po[i][3] += a[i] * b.w;
            }
        }
#pragma unroll
        for (int i = 0; i < 8; i++) {
            float4 o = make_float4(po[i][0], po[i][1], po[i][2], po[i][3]);
            *(float4*)&res[((size_t)bn * SS + r0 + i) * DD + h * DKV + cv] = o;
        }
    }
}

// ---------------- residual + LayerNorm ----------------
__global__ __launch_bounds__(256) void ln_kernel(
    const float* __restrict__ O, const float* __restrict__ X,
    const float* __restrict__ gamma, const float* __restrict__ beta,
    float* __restrict__ Y)
{
    __shared__ float red[256];
    size_t base = (size_t)blockIdx.x * DD;
    int t = threadIdx.x;
    float x0 = O[base + t]       + X[base + t];
    float x1 = O[base + t + 256] + X[base + t + 256];

    red[t] = x0 + x1;
    __syncthreads();
    for (int o = 128; o > 0; o >>= 1) {
        if (t < o) red[t] += red[t + o];
        __syncthreads();
    }
    float mean = red[0] * (1.0f / DD);
    __syncthreads();

    float d0 = x0 - mean, d1 = x1 - mean;
    red[t] = d0 * d0 + d1 * d1;
    __syncthreads();
    for (int o = 128; o > 0; o >>= 1) {
        if (t < o) red[t] += red[t + o];
        __syncthreads();
    }
    float var = red[0] * (1.0f / DD);
    float inv = rsqrtf(var + 1e-5f);

    Y[base + t]       = d0 * inv * gamma[t]       + beta[t];
    Y[base + t + 256] = d1 * inv * gamma[t + 256] + beta[t + 256];
}

// ---------------- launch ----------------
extern "C" void kernel_launch(void* const* d_in, const int* in_sizes, int n_in,
                              void* d_out, int out_size)
{
    const float* Q     = (const float*)d_in[0];
    const float* K     = (const float*)d_in[1];
    const float* V     = (const float*)d_in[2];
    const void*  mask  = d_in[3];
    const float* WQ    = (const float*)d_in[4];
    const float* WK    = (const float*)d_in[5];
    const float* WV    = (const float*)d_in[6];
    const float* Wfc   = (const float*)d_in[7];
    const float* gamma = (const float*)d_in[8];
    const float* beta  = (const float*)d_in[9];

    float* y    = (float*)d_out;
    float* attn = y + (size_t)YSIZE;

    cudaFuncSetAttribute(attn_kernel, cudaFuncAttributeMaxDynamicSharedMemorySize, ATTN_SMEM);

    void *pQp, *pKp, *pVp, *pRes, *pOutp;
    cudaGetSymbolAddress(&pQp,  g_Qp);
    cudaGetSymbolAddress(&pKp,  g_Kp);
    cudaGetSymbolAddress(&pVp,  g_Vp);
    cudaGetSymbolAddress(&pRes, g_res);
    cudaGetSymbolAddress(&pOutp,g_outp);

    detect_mask_kernel<<<1, 256>>>((const unsigned int*)mask, 65536);

    dim3 g(NTOK / 128, DD / 128);  // (512, 4)
    gemm_bf16s<<<g, 256>>>(Q, WQ, (float*)pQp, NTOK, DD, DD);
    gemm_bf16s<<<g, 256>>>(K, WK, (float*)pKp, NTOK, DD, DD);
    gemm_bf16s<<<g, 256>>>(V, WV, (float*)pVp, NTOK, DD, DD);

    attn_kernel<<<BB * NNN * HH, 256, ATTN_SMEM>>>(
        (const float*)pQp, (const float*)pKp, (const float*)pVp, mask, attn, (float*)pRes);

    gemm_bf16s<<<g, 256>>>((const float*)pRes, Wfc, (float*)pOutp, NTOK, DD, DD);

    ln_kernel<<<NTOK, 256>>>((const float*)pOutp, Q, gamma, beta, y);
}

// round 3
// speedup vs baseline: 1.8358x; 1.0413x over previous
#include <cuda_runtime.h>
#include <cuda_bf16.h>
#include <cstdint>

#define BB   16
#define NNN  32
#define SS   128
#define DD   512
#define HH   8
#define DKV  64
#define NTOK (BB*NNN*SS)          // 65536
#define YSIZE  (NTOK*DD)          // 33554432

typedef __nv_bfloat16 bf16;

// ---------------- scratch (static __device__, no cudaMalloc) ----------------
__device__ bf16 g_inhi[3ull*NTOK*DD];
__device__ bf16 g_inlo[3ull*NTOK*DD];
__device__ bf16 g_whi[4ull*DD*DD];
__device__ bf16 g_wlo[4ull*DD*DD];
__device__ bf16 g_pjhi[3ull*NTOK*DD];   // Q,K,V projections (split)
__device__ bf16 g_pjlo[3ull*NTOK*DD];
__device__ bf16 g_reshi[(size_t)NTOK*DD];
__device__ bf16 g_reslo[(size_t)NTOK*DD];
__device__ float g_outp[(size_t)NTOK*DD];
__device__ int  g_mask_kind;   // 0=int32, 1=float32, 2=uint8

// ---------------- mask dtype detection ----------------
__global__ void detect_mask_kernel(const unsigned int* __restrict__ mw, int nwords) {
    __shared__ int s_not01, s_isfloat;
    if (threadIdx.x == 0) { s_not01 = 0; s_isfloat = 0; }
    __syncthreads();
    for (int i = threadIdx.x; i < nwords; i += blockDim.x) {
        unsigned v = mw[i];
        if (v == 0x3f800000u) s_isfloat = 1;
        else if (v > 1u) s_not01 = 1;
    }
    __syncthreads();
    if (threadIdx.x == 0) g_mask_kind = s_not01 ? 2 : (s_isfloat ? 1 : 0);
}

// ---------------- bf16 helpers ----------------
__device__ __forceinline__ unsigned pack_bf16(float lo, float hi) {
    unsigned d;
    asm("cvt.rn.bf16x2.f32 %0, %1, %2;" : "=r"(d) : "f"(hi), "f"(lo));
    return d;
}
__device__ __forceinline__ float bf_lo_f(unsigned p) { return __uint_as_float(p << 16); }
__device__ __forceinline__ float bf_hi_f(unsigned p) { return __uint_as_float(p & 0xFFFF0000u); }

__device__ __forceinline__ void mma16816(float c[4],
    unsigned a0, unsigned a1, unsigned a2, unsigned a3, unsigned b0, unsigned b1)
{
    asm volatile(
        "mma.sync.aligned.m16n8k16.row.col.f32.bf16.bf16.f32 "
        "{%0,%1,%2,%3}, {%4,%5,%6,%7}, {%8,%9}, {%0,%1,%2,%3};"
        : "+f"(c[0]), "+f"(c[1]), "+f"(c[2]), "+f"(c[3])
        : "r"(a0), "r"(a1), "r"(a2), "r"(a3), "r"(b0), "r"(b1));
}

__device__ __forceinline__ void cpa16(uint32_t s, const void* g) {
    asm volatile("cp.async.cg.shared.global [%0], [%1], 16;" :: "r"(s), "l"(g));
}

// ---------------- split fp32 -> bf16 hi/lo ----------------
__global__ __launch_bounds__(256) void split_kernel(
    const float* __restrict__ src, bf16* __restrict__ hi, bf16* __restrict__ lo, int n4)
{
    int i = blockIdx.x * 256 + threadIdx.x;
    if (i >= n4) return;
    float4 v = ((const float4*)src)[i];
    unsigned h01 = pack_bf16(v.x, v.y), h23 = pack_bf16(v.z, v.w);
    unsigned l01 = pack_bf16(v.x - bf_lo_f(h01), v.y - bf_hi_f(h01));
    unsigned l23 = pack_bf16(v.z - bf_lo_f(h23), v.w - bf_hi_f(h23));
    ((uint2*)hi)[i] = make_uint2(h01, h23);
    ((uint2*)lo)[i] = make_uint2(l01, l23);
}

// ---------------- GEMM: bf16x3 split inputs, cp.async double buffer ----------------
// C[m][n] = sum_k A[m][k]*B[n][k].  grid = (N/128, M/128)
#define GEMM_SMEM (2*4*5120*2)   // 81920 bytes

template<bool SPLIT_OUT>
__global__ __launch_bounds__(256, 2) void gemm_sp(
    const bf16* __restrict__ Ahi, const bf16* __restrict__ Alo,
    const bf16* __restrict__ Bhi, const bf16* __restrict__ Blo,
    float* __restrict__ C, bf16* __restrict__ Chi, bf16* __restrict__ Clo,
    int M, int N, int K)
{
    extern __shared__ bf16 gsm[];
    const int tid = threadIdx.x;
    const int lane = tid & 31, wid = tid >> 5;
    const int wm = wid & 1, wn = wid >> 1;
    const int g = lane >> 2, q = lane & 3;
    const int n0 = blockIdx.x * 128, m0 = blockIdx.y * 128;
    uint32_t sbase = (uint32_t)__cvta_generic_to_shared(gsm);

    const bf16* srcs[4] = {Ahi, Alo, Bhi, Blo};
    const int rb[4] = {m0, m0, n0, n0};

    auto issue = [&](int buf, int k0) {
#pragma unroll
        for (int mm = 0; mm < 4; mm++) {
#pragma unroll
            for (int j = 0; j < 2; j++) {
                int cc = tid + j * 256;
                int row = cc >> 2, off = (cc & 3) << 3;
                const bf16* gp = srcs[mm] + (size_t)(rb[mm] + row) * K + k0 + off;
                uint32_t sa = sbase + (((buf * 4 + mm) * 5120) + row * 40 + off) * 2;
                cpa16(sa, gp);
            }
        }
        asm volatile("cp.async.commit_group;");
    };

    float acc[4][4][4] = {};
    const int nIter = K >> 5;
    issue(0, 0);
    issue(1, 32);

    for (int it = 0; it < nIter; it++) {
        if (it + 1 < nIter) asm volatile("cp.async.wait_group 1;");
        else                asm volatile("cp.async.wait_group 0;");
        __syncthreads();
        const bf16* pAhi = gsm + (size_t)(it & 1) * 4 * 5120;
        const bf16* pAlo = pAhi + 5120;
        const bf16* pBhi = pAhi + 2 * 5120;
        const bf16* pBlo = pAhi + 3 * 5120;
#pragma unroll
        for (int kb = 0; kb < 32; kb += 16) {
            int kk = kb + 2 * q;
            unsigned af[4][8];
#pragma unroll
            for (int i = 0; i < 4; i++) {
                int r0 = wm * 64 + i * 16 + g;
                af[i][0] = *(const unsigned*)&pAhi[r0 * 40 + kk];
                af[i][1] = *(const unsigned*)&pAhi[(r0 + 8) * 40 + kk];
                af[i][2] = *(const unsigned*)&pAhi[r0 * 40 + kk + 8];
                af[i][3] = *(const unsigned*)&pAhi[(r0 + 8) * 40 + kk + 8];
                af[i][4] = *(const unsigned*)&pAlo[r0 * 40 + kk];
                af[i][5] = *(const unsigned*)&pAlo[(r0 + 8) * 40 + kk];
                af[i][6] = *(const unsigned*)&pAlo[r0 * 40 + kk + 8];
                af[i][7] = *(const unsigned*)&pAlo[(r0 + 8) * 40 + kk + 8];
            }
#pragma unroll
            for (int j = 0; j < 4; j++) {
                int nr = wn * 32 + j * 8 + g;
                unsigned bh0 = *(const unsigned*)&pBhi[nr * 40 + kk];
                unsigned bh1 = *(const unsigned*)&pBhi[nr * 40 + kk + 8];
                unsigned bl0 = *(const unsigned*)&pBlo[nr * 40 + kk];
                unsigned bl1 = *(const unsigned*)&pBlo[nr * 40 + kk + 8];
#pragma unroll
                for (int i = 0; i < 4; i++) {
                    mma16816(acc[i][j], af[i][0], af[i][1], af[i][2], af[i][3], bh0, bh1);
                    mma16816(acc[i][j], af[i][0], af[i][1], af[i][2], af[i][3], bl0, bl1);
                    mma16816(acc[i][j], af[i][4], af[i][5], af[i][6], af[i][7], bh0, bh1);
                }
            }
        }
        __syncthreads();
        if (it + 2 < nIter) issue(it & 1, (it + 2) << 5);
    }

#pragma unroll
    for (int i = 0; i < 4; i++) {
#pragma unroll
        for (int j = 0; j < 4; j++) {
            int row = m0 + wm * 64 + i * 16 + g;
            int col = n0 + wn * 32 + j * 8 + 2 * q;
            if (SPLIT_OUT) {
                unsigned h01 = pack_bf16(acc[i][j][0], acc[i][j][1]);
                unsigned l01 = pack_bf16(acc[i][j][0] - bf_lo_f(h01), acc[i][j][1] - bf_hi_f(h01));
                unsigned h23 = pack_bf16(acc[i][j][2], acc[i][j][3]);
                unsigned l23 = pack_bf16(acc[i][j][2] - bf_lo_f(h23), acc[i][j][3] - bf_hi_f(h23));
                *(unsigned*)&Chi[(size_t)row * N + col]       = h01;
                *(unsigned*)&Clo[(size_t)row * N + col]       = l01;
                *(unsigned*)&Chi[(size_t)(row + 8) * N + col] = h23;
                *(unsigned*)&Clo[(size_t)(row + 8) * N + col] = l23;
            } else {
                *(float2*)&C[(size_t)row * N + col]       = make_float2(acc[i][j][0], acc[i][j][1]);
                *(float2*)&C[(size_t)(row + 8) * N + col] = make_float2(acc[i][j][2], acc[i][j][3]);
            }
        }
    }
}

// ---------------- attention (tensor core) ----------------
// smem: Qhi/Qlo/Khi/Klo [128][72] bf16; Vt hi/lo [64][136]; P [128][129] f32; mask u8 [128][128]
// Phi aliases Q region, Plo aliases K region (post-QK).
#define ATTN_SMEM 190976

__global__ __launch_bounds__(256, 1) void attn_mma(
    const bf16* __restrict__ pjhi, const bf16* __restrict__ pjlo,
    const void* __restrict__ mask, float* __restrict__ attn_out,
    bf16* __restrict__ res_hi, bf16* __restrict__ res_lo)
{
    extern __shared__ char smc[];
    bf16* sQhi = (bf16*)smc;
    bf16* sQlo = sQhi + 128 * 72;
    bf16* sKhi = sQlo + 128 * 72;
    bf16* sKlo = sKhi + 128 * 72;
    bf16* sVhi = sKlo + 128 * 72;      // [64][136] (dv-major, transposed)
    bf16* sVlo = sVhi + 64 * 136;
    float* P   = (float*)(sVlo + 64 * 136);
    unsigned char* sMask = (unsigned char*)(P + 128 * 129);
    bf16* sPhi = sQhi;   // alias (spans Qhi+Qlo: 18432 >= 17408)
    bf16* sPlo = sKhi;   // alias (spans Khi+Klo)

    int tid = threadIdx.x;
    int lane = tid & 31, wid = tid >> 5;
    int g = lane >> 2, q = lane & 3;
    int bn = blockIdx.x >> 3, h = blockIdx.x & 7;
    int kind = g_mask_kind;

    const size_t base = (size_t)bn * 128 * DD + (size_t)h * 64;
    const bf16* Qh = pjhi + base;
    const bf16* Ql = pjlo + base;
    const bf16* Kh = pjhi + (size_t)NTOK * DD + base;
    const bf16* Kl = pjlo + (size_t)NTOK * DD + base;
    const bf16* Vh = pjhi + 2ull * NTOK * DD + base;
    const bf16* Vl = pjlo + 2ull * NTOK * DD + base;

    // load Q,K tiles (row-major, stride 72)
    for (int i = tid; i < 2048; i += 256) {
        int r = i >> 4, c4 = (i & 15) << 2;
        size_t go = (size_t)r * DD + c4;
        *(uint2*)&sQhi[r * 72 + c4] = *(const uint2*)&Qh[go];
        *(uint2*)&sQlo[r * 72 + c4] = *(const uint2*)&Ql[go];
        *(uint2*)&sKhi[r * 72 + c4] = *(const uint2*)&Kh[go];
        *(uint2*)&sKlo[r * 72 + c4] = *(const uint2*)&Kl[go];
    }
    // load V transposed to [dv][t]
    for (int i = tid; i < 2048; i += 256) {
        int t = i >> 4, c4 = (i & 15) << 2;
        size_t go = (size_t)t * DD + c4;
        uint2 vh = *(const uint2*)&Vh[go];
        uint2 vl = *(const uint2*)&Vl[go];
        bf16 bh[4], bl[4];
        *(uint2*)bh = vh; *(uint2*)bl = vl;
#pragma unroll
        for (int d = 0; d < 4; d++) {
            sVhi[(c4 + d) * 136 + t] = bh[d];
            sVlo[(c4 + d) * 136 + t] = bl[d];
        }
    }
    // mask -> smem u8
    {
        size_t mb = (size_t)bn * (128 * 128);
        if (kind == 2) {
            const unsigned* mw = (const unsigned*)mask + (mb >> 2);
            unsigned* dw = (unsigned*)sMask;
            for (int i = tid; i < 4096; i += 256) dw[i] = mw[i];
        } else if (kind == 1) {
            const float* mf = (const float*)mask + mb;
            for (int i = tid; i < 16384; i += 256) sMask[i] = (mf[i] != 0.0f);
        } else {
            const int* mi = (const int*)mask + mb;
            for (int i = tid; i < 16384; i += 256) sMask[i] = (mi[i] != 0);
        }
    }
    __syncthreads();

    // ---- QK^T (bf16x3) ----
    {
        int wm = wid & 1, wn = wid >> 1;
        float acc[4][4][4] = {};
#pragma unroll
        for (int kb = 0; kb < 64; kb += 16) {
            int kk = kb + 2 * q;
            unsigned af[4][8];
#pragma unroll
            for (int i = 0; i < 4; i++) {
                int r0 = wm * 64 + i * 16 + g;
                af[i][0] = *(const unsigned*)&sQhi[r0 * 72 + kk];
                af[i][1] = *(const unsigned*)&sQhi[(r0 + 8) * 72 + kk];
                af[i][2] = *(const unsigned*)&sQhi[r0 * 72 + kk + 8];
                af[i][3] = *(const unsigned*)&sQhi[(r0 + 8) * 72 + kk + 8];
                af[i][4] = *(const unsigned*)&sQlo[r0 * 72 + kk];
                af[i][5] = *(const unsigned*)&sQlo[(r0 + 8) * 72 + kk];
                af[i][6] = *(const unsigned*)&sQlo[r0 * 72 + kk + 8];
                af[i][7] = *(const unsigned*)&sQlo[(r0 + 8) * 72 + kk + 8];
            }
#pragma unroll
            for (int j = 0; j < 4; j++) {
                int nr = wn * 32 + j * 8 + g;
                unsigned bh0 = *(const unsigned*)&sKhi[nr * 72 + kk];
                unsigned bh1 = *(const unsigned*)&sKhi[nr * 72 + kk + 8];
                unsigned bl0 = *(const unsigned*)&sKlo[nr * 72 + kk];
                unsigned bl1 = *(const unsigned*)&sKlo[nr * 72 + kk + 8];
#pragma unroll
                for (int i = 0; i < 4; i++) {
                    mma16816(acc[i][j], af[i][0], af[i][1], af[i][2], af[i][3], bh0, bh1);
                    mma16816(acc[i][j], af[i][0], af[i][1], af[i][2], af[i][3], bl0, bl1);
                    mma16816(acc[i][j], af[i][4], af[i][5], af[i][6], af[i][7], bh0, bh1);
                }
            }
        }
#pragma unroll
        for (int i = 0; i < 4; i++)
#pragma unroll
            for (int j = 0; j < 4; j++) {
                int r = wm * 64 + i * 16 + g, c = wn * 32 + j * 8 + 2 * q;
                P[r * 129 + c]           = acc[i][j][0] * 0.125f;
                P[r * 129 + c + 1]       = acc[i][j][1] * 0.125f;
                P[(r + 8) * 129 + c]     = acc[i][j][2] * 0.125f;
                P[(r + 8) * 129 + c + 1] = acc[i][j][3] * 0.125f;
            }
    }
    __syncthreads();

    // ---- mask + softmax (warp per row) ----
    for (int rr = 0; rr < 16; rr++) {
        int r = wid * 16 + rr;
        float v[4];
#pragma unroll
        for (int k = 0; k < 4; k++) {
            int c = lane + 32 * k;
            v[k] = sMask[r * 128 + c] ? P[r * 129 + c] : -1e9f;
        }
        float mx = fmaxf(fmaxf(v[0], v[1]), fmaxf(v[2], v[3]));
#pragma unroll
        for (int o = 16; o; o >>= 1) mx = fmaxf(mx, __shfl_xor_sync(0xffffffffu, mx, o));
        float s = 0.f;
#pragma unroll
        for (int k = 0; k < 4; k++) { v[k] = __expf(v[k] - mx); s += v[k]; }
#pragma unroll
        for (int o = 16; o; o >>= 1) s += __shfl_xor_sync(0xffffffffu, s, o);
        float inv = 1.0f / s;
#pragma unroll
        for (int k = 0; k < 4; k++) P[r * 129 + lane + 32 * k] = v[k] * inv;
    }
    __syncthreads();

    // ---- attn output write + P -> Phi/Plo split ----
    {
        float* aout = attn_out + (size_t)blockIdx.x * (128 * 128);
        for (int i = tid; i < 16384; i += 256) {
            int r = i >> 7, c = i & 127;
            aout[i] = P[r * 129 + c];
        }
        for (int i = tid; i < 8192; i += 256) {
            int r = i >> 6, c2 = (i & 63) << 1;
            float p0 = P[r * 129 + c2], p1 = P[r * 129 + c2 + 1];
            unsigned hh = pack_bf16(p0, p1);
            unsigned ll = pack_bf16(p0 - bf_lo_f(hh), p1 - bf_hi_f(hh));
            *(unsigned*)&sPhi[r * 136 + c2] = hh;
            *(unsigned*)&sPlo[r * 136 + c2] = ll;
        }
    }
    __syncthreads();

    // ---- P @ V (bf16x3) ----
    {
        int wm = wid & 1, wn = wid >> 1;
        float acc[4][2][4] = {};
#pragma unroll
        for (int kb = 0; kb < 128; kb += 16) {
            int kk = kb + 2 * q;
            unsigned af[4][8];
#pragma unroll
            for (int i = 0; i < 4; i++) {
                int r0 = wm * 64 + i * 16 + g;
                af[i][0] = *(const unsigned*)&sPhi[r0 * 136 + kk];
                af[i][1] = *(const unsigned*)&sPhi[(r0 + 8) * 136 + kk];
                af[i][2] = *(const unsigned*)&sPhi[r0 * 136 + kk + 8];
                af[i][3] = *(const unsigned*)&sPhi[(r0 + 8) * 136 + kk + 8];
                af[i][4] = *(const unsigned*)&sPlo[r0 * 136 + kk];
                af[i][5] = *(const unsigned*)&sPlo[(r0 + 8) * 136 + kk];
                af[i][6] = *(const unsigned*)&sPlo[r0 * 136 + kk + 8];
                af[i][7] = *(const unsigned*)&sPlo[(r0 + 8) * 136 + kk + 8];
            }
#pragma unroll
            for (int j = 0; j < 2; j++) {
                int nr = wn * 16 + j * 8 + g;
                unsigned bh0 = *(const unsigned*)&sVhi[nr * 136 + kk];
                unsigned bh1 = *(const unsigned*)&sVhi[nr * 136 + kk + 8];
                unsigned bl0 = *(const unsigned*)&sVlo[nr * 136 + kk];
                unsigned bl1 = *(const unsigned*)&sVlo[nr * 136 + kk + 8];
#pragma unroll
                for (int i = 0; i < 4; i++) {
                    mma16816(acc[i][j], af[i][0], af[i][1], af[i][2], af[i][3], bh0, bh1);
                    mma16816(acc[i][j], af[i][0], af[i][1], af[i][2], af[i][3], bl0, bl1);
                    mma16816(acc[i][j], af[i][4], af[i][5], af[i][6], af[i][7], bh0, bh1);
                }
            }
        }
#pragma unroll
        for (int i = 0; i < 4; i++)
#pragma unroll
            for (int j = 0; j < 2; j++) {
                int row = wm * 64 + i * 16 + g, col = wn * 16 + j * 8 + 2 * q;
                size_t o0 = ((size_t)(bn * 128 + row)) * DD + h * 64 + col;
                size_t o1 = ((size_t)(bn * 128 + row + 8)) * DD + h * 64 + col;
                unsigned h01 = pack_bf16(acc[i][j][0], acc[i][j][1]);
                unsigned l01 = pack_bf16(acc[i][j][0] - bf_lo_f(h01), acc[i][j][1] - bf_hi_f(h01));
                unsigned h23 = pack_bf16(acc[i][j][2], acc[i][j][3]);
                unsigned l23 = pack_bf16(acc[i][j][2] - bf_lo_f(h23), acc[i][j][3] - bf_hi_f(h23));
                *(unsigned*)&res_hi[o0] = h01; *(unsigned*)&res_lo[o0] = l01;
                *(unsigned*)&res_hi[o1] = h23; *(unsigned*)&res_lo[o1] = l23;
            }
    }
}

// ---------------- residual + LayerNorm ----------------
__global__ __launch_bounds__(256) void ln_kernel(
    const float* __restrict__ O, const float* __restrict__ X,
    const float* __restrict__ gamma, const float* __restrict__ beta,
    float* __restrict__ Y)
{
    __shared__ float red[256];
    size_t base = (size_t)blockIdx.x * DD;
    int t = threadIdx.x;
    float x0 = O[base + t]       + X[base + t];
    float x1 = O[base + t + 256] + X[base + t + 256];

    red[t] = x0 + x1;
    __syncthreads();
    for (int o = 128; o > 0; o >>= 1) {
        if (t < o) red[t] += red[t + o];
        __syncthreads();
    }
    float mean = red[0] * (1.0f / DD);
    __syncthreads();

    float d0 = x0 - mean, d1 = x1 - mean;
    red[t] = d0 * d0 + d1 * d1;
    __syncthreads();
    for (int o = 128; o > 0; o >>= 1) {
        if (t < o) red[t] += red[t + o];
        __syncthreads();
    }
    float var = red[0] * (1.0f / DD);
    float inv = rsqrtf(var + 1e-5f);

    Y[base + t]       = d0 * inv * gamma[t]       + beta[t];
    Y[base + t + 256] = d1 * inv * gamma[t + 256] + beta[t + 256];
}

// ---------------- launch ----------------
extern "C" void kernel_launch(void* const* d_in, const int* in_sizes, int n_in,
                              void* d_out, int out_size)
{
    const float* Q     = (const float*)d_in[0];
    const float* K     = (const float*)d_in[1];
    const float* V     = (const float*)d_in[2];
    const void*  mask  = d_in[3];
    const float* WQ    = (const float*)d_in[4];
    const float* WK    = (const float*)d_in[5];
    const float* WV    = (const float*)d_in[6];
    const float* Wfc   = (const float*)d_in[7];
    const float* gamma = (const float*)d_in[8];
    const float* beta  = (const float*)d_in[9];

    float* y    = (float*)d_out;
    float* attn = y + (size_t)YSIZE;

    void *p;
    cudaGetSymbolAddress(&p, g_inhi);  bf16* inhi = (bf16*)p;
    cudaGetSymbolAddress(&p, g_inlo);  bf16* inlo = (bf16*)p;
    cudaGetSymbolAddress(&p, g_whi);   bf16* whi  = (bf16*)p;
    cudaGetSymbolAddress(&p, g_wlo);   bf16* wlo  = (bf16*)p;
    cudaGetSymbolAddress(&p, g_pjhi);  bf16* pjhi = (bf16*)p;
    cudaGetSymbolAddress(&p, g_pjlo);  bf16* pjlo = (bf16*)p;
    cudaGetSymbolAddress(&p, g_reshi); bf16* reshi= (bf16*)p;
    cudaGetSymbolAddress(&p, g_reslo); bf16* reslo= (bf16*)p;
    cudaGetSymbolAddress(&p, g_outp);  float* outp= (float*)p;

    cudaFuncSetAttribute(gemm_sp<true>,  cudaFuncAttributeMaxDynamicSharedMemorySize, GEMM_SMEM);
    cudaFuncSetAttribute(gemm_sp<false>, cudaFuncAttributeMaxDynamicSharedMemorySize, GEMM_SMEM);
    cudaFuncSetAttribute(attn_mma, cudaFuncAttributeMaxDynamicSharedMemorySize, ATTN_SMEM);

    detect_mask_kernel<<<1, 256>>>((const unsigned int*)mask, 65536);

    const size_t NE = (size_t)NTOK * DD;   // 33.5M
    const int n4 = (int)(NE / 4);
    split_kernel<<<n4 / 256, 256>>>(Q, inhi,          inlo,          n4);
    split_kernel<<<n4 / 256, 256>>>(K, inhi + NE,     inlo + NE,     n4);
    split_kernel<<<n4 / 256, 256>>>(V, inhi + 2 * NE, inlo + 2 * NE, n4);
    const size_t WE = (size_t)DD * DD;
    const int w4 = (int)(WE / 4);
    split_kernel<<<w4 / 256, 256>>>(WQ,  whi,          wlo,          w4);
    split_kernel<<<w4 / 256, 256>>>(WK,  whi + WE,     wlo + WE,     w4);
    split_kernel<<<w4 / 256, 256>>>(WV,  whi + 2 * WE, wlo + 2 * WE, w4);
    split_kernel<<<w4 / 256, 256>>>(Wfc, whi + 3 * WE, wlo + 3 * WE, w4);

    dim3 gg(DD / 128, NTOK / 128);  // (4, 512): n-tile fastest -> A reuse in L2
    gemm_sp<true><<<gg, 256, GEMM_SMEM>>>(inhi,          inlo,          whi,          wlo,
                                          nullptr, pjhi,          pjlo,          NTOK, DD, DD);
    gemm_sp<true><<<gg, 256, GEMM_SMEM>>>(inhi + NE,     inlo + NE,     whi + WE,     wlo + WE,
                                          nullptr, pjhi + NE,     pjlo + NE,     NTOK, DD, DD);
    gemm_sp<true><<<gg, 256, GEMM_SMEM>>>(inhi + 2 * NE, inlo + 2 * NE, whi + 2 * WE, wlo + 2 * WE,
                                          nullptr, pjhi + 2 * NE, pjlo + 2 * NE, NTOK, DD, DD);

    attn_mma<<<BB * NNN * HH, 256, ATTN_SMEM>>>(pjhi, pjlo, mask, attn, reshi, reslo);

    gemm_sp<false><<<gg, 256, GEMM_SMEM>>>(reshi, reslo, whi + 3 * WE, wlo + 3 * WE,
                                           outp, nullptr, nullptr, NTOK, DD, DD);

    ln_kernel<<<NTOK, 256>>>(outp, Q, gamma, beta, y);
}

// round 4
// speedup vs baseline: 2.3706x; 1.2913x over previous
#include <cuda_runtime.h>
#include <cuda_bf16.h>
#include <cstdint>

#define BB   16
#define NNN  32
#define SS   128
#define DD   512
#define HH   8
#define NTOK (BB*NNN*SS)          // 65536
#define YSIZE  (NTOK*DD)          // 33554432

typedef __nv_bfloat16 bf16;

// ---------------- scratch ----------------
__device__ bf16 g_inhi[3ull*NTOK*DD];
__device__ bf16 g_inlo[3ull*NTOK*DD];
__device__ bf16 g_whi[4ull*DD*DD];
__device__ bf16 g_wlo[4ull*DD*DD];
__device__ bf16 g_pjhi[3ull*NTOK*DD];
__device__ bf16 g_pjlo[3ull*NTOK*DD];
__device__ bf16 g_reshi[(size_t)NTOK*DD];
__device__ bf16 g_reslo[(size_t)NTOK*DD];
__device__ float g_outp[(size_t)NTOK*DD];
__device__ int  g_mask_kind;

// ---------------- mask dtype detection ----------------
__global__ void detect_mask_kernel(const unsigned int* __restrict__ mw, int nwords) {
    __shared__ int s_not01, s_isfloat;
    if (threadIdx.x == 0) { s_not01 = 0; s_isfloat = 0; }
    __syncthreads();
    for (int i = threadIdx.x; i < nwords; i += blockDim.x) {
        unsigned v = mw[i];
        if (v == 0x3f800000u) s_isfloat = 1;
        else if (v > 1u) s_not01 = 1;
    }
    __syncthreads();
    if (threadIdx.x == 0) g_mask_kind = s_not01 ? 2 : (s_isfloat ? 1 : 0);
}

// ---------------- helpers ----------------
__device__ __forceinline__ unsigned pack_bf16(float lo, float hi) {
    unsigned d;
    asm("cvt.rn.bf16x2.f32 %0, %1, %2;" : "=r"(d) : "f"(hi), "f"(lo));
    return d;
}
__device__ __forceinline__ float bf_lo_f(unsigned p) { return __uint_as_float(p << 16); }
__device__ __forceinline__ float bf_hi_f(unsigned p) { return __uint_as_float(p & 0xFFFF0000u); }

__device__ __forceinline__ void mma16816(float c[4],
    unsigned a0, unsigned a1, unsigned a2, unsigned a3, unsigned b0, unsigned b1)
{
    asm volatile(
        "mma.sync.aligned.m16n8k16.row.col.f32.bf16.bf16.f32 "
        "{%0,%1,%2,%3}, {%4,%5,%6,%7}, {%8,%9}, {%0,%1,%2,%3};"
        : "+f"(c[0]), "+f"(c[1]), "+f"(c[2]), "+f"(c[3])
        : "r"(a0), "r"(a1), "r"(a2), "r"(a3), "r"(b0), "r"(b1));
}
__device__ __forceinline__ void cpa16(uint32_t s, const void* g) {
    asm volatile("cp.async.cg.shared.global [%0], [%1], 16;" :: "r"(s), "l"(g));
}
__device__ __forceinline__ void ldsm4(unsigned& r0, unsigned& r1, unsigned& r2, unsigned& r3, uint32_t a) {
    asm volatile("ldmatrix.sync.aligned.m8n8.x4.shared.b16 {%0,%1,%2,%3}, [%4];"
        : "=r"(r0), "=r"(r1), "=r"(r2), "=r"(r3) : "r"(a));
}
__device__ __forceinline__ void ldsm4t(unsigned& r0, unsigned& r1, unsigned& r2, unsigned& r3, uint32_t a) {
    asm volatile("ldmatrix.sync.aligned.m8n8.x4.trans.shared.b16 {%0,%1,%2,%3}, [%4];"
        : "=r"(r0), "=r"(r1), "=r"(r2), "=r"(r3) : "r"(a));
}

// ---------------- split fp32 -> bf16 hi/lo ----------------
__global__ __launch_bounds__(256) void split_kernel(
    const float* __restrict__ src, bf16* __restrict__ hi, bf16* __restrict__ lo, int n4)
{
    int i = blockIdx.x * 256 + threadIdx.x;
    if (i >= n4) return;
    float4 v = ((const float4*)src)[i];
    unsigned h01 = pack_bf16(v.x, v.y), h23 = pack_bf16(v.z, v.w);
    unsigned l01 = pack_bf16(v.x - bf_lo_f(h01), v.y - bf_hi_f(h01));
    unsigned l23 = pack_bf16(v.z - bf_lo_f(h23), v.w - bf_hi_f(h23));
    ((uint2*)hi)[i] = make_uint2(h01, h23);
    ((uint2*)lo)[i] = make_uint2(l01, l23);
}

// ---------------- GEMM: bf16x3, cp.async double buffer, ldmatrix ----------------
// Tiles: 128 rows x 32 bf16 (64B rows), swizzle: ch ^= (row>>1)&3
#define GEMM_SMEM 65536

template<bool SPLIT_OUT>
__global__ __launch_bounds__(256, 2) void gemm_sp(
    const bf16* __restrict__ Ahi, const bf16* __restrict__ Alo,
    const bf16* __restrict__ Bhi, const bf16* __restrict__ Blo,
    float* __restrict__ C, bf16* __restrict__ Chi, bf16* __restrict__ Clo,
    int M, int N, int K)
{
    extern __shared__ bf16 gsm[];
    const int tid = threadIdx.x;
    const int lane = tid & 31, wid = tid >> 5;
    const int wm = wid & 1, wn = wid >> 1;
    const int g = lane >> 2, q = lane & 3;
    const int lrow = (lane & 7) + ((lane >> 3) & 1) * 8;
    const int lch  = lane >> 4;
    const int n0 = blockIdx.x * 128, m0 = blockIdx.y * 128;
    uint32_t sb = (uint32_t)__cvta_generic_to_shared(gsm);

    const bf16* srcs[4] = {Ahi, Alo, Bhi, Blo};
    const int rb[4] = {m0, m0, n0, n0};

    auto issue = [&](int buf, int k0) {
#pragma unroll
        for (int mm = 0; mm < 4; mm++) {
#pragma unroll
            for (int j = 0; j < 2; j++) {
                int cc = tid + j * 256;
                int row = cc >> 2, ch = cc & 3;
                const bf16* gp = srcs[mm] + (size_t)(rb[mm] + row) * K + k0 + ch * 8;
                uint32_t sa = sb + buf * 32768 + mm * 8192 + row * 64
                            + (((ch ^ ((row >> 1) & 3))) << 4);
                cpa16(sa, gp);
            }
        }
        asm volatile("cp.async.commit_group;");
    };

    float acc[4][4][4] = {};
    const int nIter = K >> 5;
    issue(0, 0);
    issue(1, 32);

    for (int it = 0; it < nIter; it++) {
        if (it + 1 < nIter) asm volatile("cp.async.wait_group 1;");
        else                asm volatile("cp.async.wait_group 0;");
        __syncthreads();
        uint32_t bufb = sb + (it & 1) * 32768;
#pragma unroll
        for (int kb = 0; kb < 32; kb += 16) {
            int c0 = kb >> 3;
            unsigned af[4][8];
#pragma unroll
            for (int i = 0; i < 4; i++) {
                int row = wm * 64 + i * 16 + lrow;
                uint32_t a = bufb + row * 64 + ((((c0 + lch) ^ ((row >> 1) & 3))) << 4);
                ldsm4(af[i][0], af[i][1], af[i][2], af[i][3], a);
                ldsm4(af[i][4], af[i][5], af[i][6], af[i][7], a + 8192);
            }
            unsigned bh[2][4], bl[2][4];
#pragma unroll
            for (int p = 0; p < 2; p++) {
                int row = wn * 32 + p * 16 + lrow;
                uint32_t b = bufb + 16384 + row * 64 + ((((c0 + lch) ^ ((row >> 1) & 3))) << 4);
                ldsm4(bh[p][0], bh[p][1], bh[p][2], bh[p][3], b);
                ldsm4(bl[p][0], bl[p][1], bl[p][2], bl[p][3], b + 8192);
            }
#pragma unroll
            for (int j = 0; j < 4; j++) {
                int p = j >> 1, o = j & 1;
                unsigned b0h = bh[p][o], b1h = bh[p][o + 2];
                unsigned b0l = bl[p][o], b1l = bl[p][o + 2];
#pragma unroll
                for (int i = 0; i < 4; i++) {
                    mma16816(acc[i][j], af[i][0], af[i][1], af[i][2], af[i][3], b0h, b1h);
                    mma16816(acc[i][j], af[i][0], af[i][1], af[i][2], af[i][3], b0l, b1l);
                    mma16816(acc[i][j], af[i][4], af[i][5], af[i][6], af[i][7], b0h, b1h);
                }
            }
        }
        __syncthreads();
        if (it + 2 < nIter) issue(it & 1, (it + 2) << 5);
    }

#pragma unroll
    for (int i = 0; i < 4; i++) {
#pragma unroll
        for (int j = 0; j < 4; j++) {
            int row = m0 + wm * 64 + i * 16 + g;
            int col = n0 + wn * 32 + j * 8 + 2 * q;
            if (SPLIT_OUT) {
                unsigned h01 = pack_bf16(acc[i][j][0], acc[i][j][1]);
                unsigned l01 = pack_bf16(acc[i][j][0] - bf_lo_f(h01), acc[i][j][1] - bf_hi_f(h01));
                unsigned h23 = pack_bf16(acc[i][j][2], acc[i][j][3]);
                unsigned l23 = pack_bf16(acc[i][j][2] - bf_lo_f(h23), acc[i][j][3] - bf_hi_f(h23));
                *(unsigned*)&Chi[(size_t)row * N + col]       = h01;
                *(unsigned*)&Clo[(size_t)row * N + col]       = l01;
                *(unsigned*)&Chi[(size_t)(row + 8) * N + col] = h23;
                *(unsigned*)&Clo[(size_t)(row + 8) * N + col] = l23;
            } else {
                *(float2*)&C[(size_t)row * N + col]       = make_float2(acc[i][j][0], acc[i][j][1]);
                *(float2*)&C[(size_t)(row + 8) * N + col] = make_float2(acc[i][j][2], acc[i][j][3]);
            }
        }
    }
}

// ---------------- attention: 64 q-rows per CTA, 2 CTAs/SM ----------------
// smem (bytes): K hi/lo @0/16384 (128x128B), V hi/lo @32768/49152 (128x128B natural [t][dv]),
// Q hi/lo @65536/73728 (64x128B) -- aliased by Psplit hi/lo after QK,
// P f32 @81920: 64 x 132 stride.  Total 115712.
#define SK_OFF 0
#define SV_OFF 32768
#define SQ_OFF 65536
#define SP_OFF 65536
#define PF_OFF 81920
#define ATTN_SMEM (PF_OFF + 64*132*4)

__global__ __launch_bounds__(256, 2) void attn_mma(
    const bf16* __restrict__ pjhi, const bf16* __restrict__ pjlo,
    const void* __restrict__ mask, float* __restrict__ attn_out,
    bf16* __restrict__ res_hi, bf16* __restrict__ res_lo)
{
    extern __shared__ char smc[];
    uint32_t sb = (uint32_t)__cvta_generic_to_shared(smc);
    float* P = (float*)(smc + PF_OFF);

    const int tid = threadIdx.x;
    const int lane = tid & 31, wid = tid >> 5;
    const int g = lane >> 2, q = lane & 3;
    const int lrow = (lane & 7) + ((lane >> 3) & 1) * 8;
    const int lch  = lane >> 4;
    const int qh = blockIdx.x & 1;
    const int h  = (blockIdx.x >> 1) & 7;
    const int bn = blockIdx.x >> 4;
    const int kind = g_mask_kind;

    const size_t base = (size_t)bn * 128 * DD + (size_t)h * 64;
    const bf16* Qh = pjhi + base;
    const bf16* Ql = pjlo + base;
    const bf16* Kh = pjhi + (size_t)NTOK * DD + base;
    const bf16* Kl = pjlo + (size_t)NTOK * DD + base;
    const bf16* Vh = pjhi + 2ull * NTOK * DD + base;
    const bf16* Vl = pjlo + 2ull * NTOK * DD + base;

    // ---- fill smem via cp.async (swizzle ch^(row&7), 128B rows) ----
    {
        // Q: 512 granules per half
#pragma unroll
        for (int t = 0; t < 2; t++) {
            int idx = tid + t * 256;
            int row = idx >> 3, ch = idx & 7;
            uint32_t sa = sb + SQ_OFF + row * 128 + (((ch ^ (row & 7))) << 4);
            size_t go = (size_t)(qh * 64 + row) * DD + ch * 8;
            cpa16(sa,        Qh + go);
            cpa16(sa + 8192, Ql + go);
        }
        // K: 1024 granules per half
#pragma unroll
        for (int t = 0; t < 4; t++) {
            int idx = tid + t * 256;
            int row = idx >> 3, ch = idx & 7;
            uint32_t sa = sb + SK_OFF + row * 128 + (((ch ^ (row & 7))) << 4);
            size_t go = (size_t)row * DD + ch * 8;
            cpa16(sa,         Kh + go);
            cpa16(sa + 16384, Kl + go);
        }
        // V: 1024 granules per half (natural [t][dv])
#pragma unroll
        for (int t = 0; t < 4; t++) {
            int idx = tid + t * 256;
            int row = idx >> 3, ch = idx & 7;
            uint32_t sa = sb + SV_OFF + row * 128 + (((ch ^ (row & 7))) << 4);
            size_t go = (size_t)row * DD + ch * 8;
            cpa16(sa,         Vh + go);
            cpa16(sa + 16384, Vl + go);
        }
        asm volatile("cp.async.commit_group;");
        asm volatile("cp.async.wait_group 0;");
    }
    __syncthreads();

    const int wm = wid & 1, wn = wid >> 1;   // 2 x 4 warp grid

    // ---- QK^T: 64 x 128, k=64 ----
    {
        float acc[2][4][4] = {};
#pragma unroll
        for (int kb = 0; kb < 64; kb += 16) {
            int c0 = kb >> 3;
            unsigned af[2][8];
#pragma unroll
            for (int i = 0; i < 2; i++) {
                int row = wm * 32 + i * 16 + lrow;
                uint32_t a = sb + SQ_OFF + row * 128 + ((((c0 + lch) ^ (row & 7))) << 4);
                ldsm4(af[i][0], af[i][1], af[i][2], af[i][3], a);
                ldsm4(af[i][4], af[i][5], af[i][6], af[i][7], a + 8192);
            }
            unsigned bh[2][4], bl[2][4];
#pragma unroll
            for (int p = 0; p < 2; p++) {
                int row = wn * 32 + p * 16 + lrow;
                uint32_t b = sb + SK_OFF + row * 128 + ((((c0 + lch) ^ (row & 7))) << 4);
                ldsm4(bh[p][0], bh[p][1], bh[p][2], bh[p][3], b);
                ldsm4(bl[p][0], bl[p][1], bl[p][2], bl[p][3], b + 16384);
            }
#pragma unroll
            for (int j = 0; j < 4; j++) {
                int p = j >> 1, o = j & 1;
                unsigned b0h = bh[p][o], b1h = bh[p][o + 2];
                unsigned b0l = bl[p][o], b1l = bl[p][o + 2];
#pragma unroll
                for (int i = 0; i < 2; i++) {
                    mma16816(acc[i][j], af[i][0], af[i][1], af[i][2], af[i][3], b0h, b1h);
                    mma16816(acc[i][j], af[i][0], af[i][1], af[i][2], af[i][3], b0l, b1l);
                    mma16816(acc[i][j], af[i][4], af[i][5], af[i][6], af[i][7], b0h, b1h);
                }
            }
        }
#pragma unroll
        for (int i = 0; i < 2; i++)
#pragma unroll
            for (int j = 0; j < 4; j++) {
                int r = wm * 32 + i * 16 + g, c = wn * 32 + j * 8 + 2 * q;
                P[r * 132 + c]           = acc[i][j][0] * 0.125f;
                P[r * 132 + c + 1]       = acc[i][j][1] * 0.125f;
                P[(r + 8) * 132 + c]     = acc[i][j][2] * 0.125f;
                P[(r + 8) * 132 + c + 1] = acc[i][j][3] * 0.125f;
            }
    }
    __syncthreads();

    // ---- mask + softmax + attn_out write (warp per row, lane -> cols 4l..4l+3) ----
    {
        float* aout = attn_out + ((size_t)(bn * 8 + h)) * 16384 + (size_t)qh * 64 * 128;
#pragma unroll
        for (int rr = 0; rr < 8; rr++) {
            int rl = wid * 8 + rr;
            int gr = qh * 64 + rl;
            float4 v = *(float4*)&P[rl * 132 + 4 * lane];
            float m0, m1, m2, m3;
            if (kind == 2) {
                uchar4 mk = ((const uchar4*)((const unsigned char*)mask + (size_t)bn * 16384 + (size_t)gr * 128))[lane];
                m0 = mk.x ? 0.f : -1e9f; m1 = mk.y ? 0.f : -1e9f;
                m2 = mk.z ? 0.f : -1e9f; m3 = mk.w ? 0.f : -1e9f;
            } else if (kind == 1) {
                float4 mk = ((const float4*)((const float*)mask + (size_t)bn * 16384 + (size_t)gr * 128))[lane];
                m0 = mk.x != 0.f ? 0.f : -1e9f; m1 = mk.y != 0.f ? 0.f : -1e9f;
                m2 = mk.z != 0.f ? 0.f : -1e9f; m3 = mk.w != 0.f ? 0.f : -1e9f;
            } else {
                int4 mk = ((const int4*)((const int*)mask + (size_t)bn * 16384 + (size_t)gr * 128))[lane];
                m0 = mk.x ? 0.f : -1e9f; m1 = mk.y ? 0.f : -1e9f;
                m2 = mk.z ? 0.f : -1e9f; m3 = mk.w ? 0.f : -1e9f;
            }
            v.x += m0; v.y += m1; v.z += m2; v.w += m3;
            float mx = fmaxf(fmaxf(v.x, v.y), fmaxf(v.z, v.w));
#pragma unroll
            for (int o = 16; o; o >>= 1) mx = fmaxf(mx, __shfl_xor_sync(0xffffffffu, mx, o));
            v.x = __expf(v.x - mx); v.y = __expf(v.y - mx);
            v.z = __expf(v.z - mx); v.w = __expf(v.w - mx);
            float s = v.x + v.y + v.z + v.w;
#pragma unroll
            for (int o = 16; o; o >>= 1) s += __shfl_xor_sync(0xffffffffu, s, o);
            float inv = 1.0f / s;
            v.x *= inv; v.y *= inv; v.z *= inv; v.w *= inv;
            *(float4*)&P[rl * 132 + 4 * lane] = v;
            *(float4*)&aout[(size_t)rl * 128 + 4 * lane] = v;
        }
    }
    __syncthreads();

    // ---- P @ V in 2 k-chunks of 64 (Psplit aliases Q region) ----
    float acc_o[2][2][4] = {};
#pragma unroll
    for (int kc = 0; kc < 2; kc++) {
        // split P chunk -> bf16 hi/lo, swizzled 128B rows
        for (int idx = tid; idx < 2048; idx += 256) {
            int row = idx >> 5, cp = (idx & 31) << 1;
            float p0 = P[row * 132 + kc * 64 + cp];
            float p1 = P[row * 132 + kc * 64 + cp + 1];
            unsigned hh = pack_bf16(p0, p1);
            unsigned ll = pack_bf16(p0 - bf_lo_f(hh), p1 - bf_hi_f(hh));
            uint32_t sa = sb + SP_OFF + row * 128 + ((((cp >> 3) ^ (row & 7))) << 4) + (cp & 7) * 2;
            *(unsigned*)(smc + (sa - sb))        = hh;
            *(unsigned*)(smc + (sa - sb) + 8192) = ll;
        }
        __syncthreads();
#pragma unroll
        for (int kb = 0; kb < 64; kb += 16) {
            int c0 = kb >> 3;
            unsigned af[2][8];
#pragma unroll
            for (int i = 0; i < 2; i++) {
                int row = wm * 32 + i * 16 + lrow;
                uint32_t a = sb + SP_OFF + row * 128 + ((((c0 + lch) ^ (row & 7))) << 4);
                ldsm4(af[i][0], af[i][1], af[i][2], af[i][3], a);
                ldsm4(af[i][4], af[i][5], af[i][6], af[i][7], a + 8192);
            }
            // V (trans): rows = t, chunks = dv/8 ; warp covers dv cols wn*16..+15
            int vrow = kc * 64 + kb + lrow;
            uint32_t vb = sb + SV_OFF + vrow * 128 + ((((wn * 2 + lch) ^ (vrow & 7))) << 4);
            unsigned vh[4], vl[4];
            ldsm4t(vh[0], vh[1], vh[2], vh[3], vb);
            ldsm4t(vl[0], vl[1], vl[2], vl[3], vb + 16384);
#pragma unroll
            for (int j = 0; j < 2; j++) {
                unsigned b0h = vh[2 * j], b1h = vh[2 * j + 1];
                unsigned b0l = vl[2 * j], b1l = vl[2 * j + 1];
#pragma unroll
                for (int i = 0; i < 2; i++) {
                    mma16816(acc_o[i][j], af[i][0], af[i][1], af[i][2], af[i][3], b0h, b1h);
                    mma16816(acc_o[i][j], af[i][0], af[i][1], af[i][2], af[i][3], b0l, b1l);
                    mma16816(acc_o[i][j], af[i][4], af[i][5], af[i][6], af[i][7], b0h, b1h);
                }
            }
        }
        __syncthreads();
    }

    // ---- epilogue: split res hi/lo ----
#pragma unroll
    for (int i = 0; i < 2; i++)
#pragma unroll
        for (int j = 0; j < 2; j++) {
            int row = wm * 32 + i * 16 + g;
            int col = h * 64 + wn * 16 + j * 8 + 2 * q;
            size_t o0 = ((size_t)(bn * 128 + qh * 64 + row)) * DD + col;
            size_t o1 = o0 + 8ull * DD;
            unsigned h01 = pack_bf16(acc_o[i][j][0], acc_o[i][j][1]);
            unsigned l01 = pack_bf16(acc_o[i][j][0] - bf_lo_f(h01), acc_o[i][j][1] - bf_hi_f(h01));
            unsigned h23 = pack_bf16(acc_o[i][j][2], acc_o[i][j][3]);
            unsigned l23 = pack_bf16(acc_o[i][j][2] - bf_lo_f(h23), acc_o[i][j][3] - bf_hi_f(h23));
            *(unsigned*)&res_hi[o0] = h01; *(unsigned*)&res_lo[o0] = l01;
            *(unsigned*)&res_hi[o1] = h23; *(unsigned*)&res_lo[o1] = l23;
        }
}

// ---------------- residual + LayerNorm ----------------
__global__ __launch_bounds__(256) void ln_kernel(
    const float* __restrict__ O, const float* __restrict__ X,
    const float* __restrict__ gamma, const float* __restrict__ beta,
    float* __restrict__ Y)
{
    __shared__ float red[256];
    size_t base = (size_t)blockIdx.x * DD;
    int t = threadIdx.x;
    float x0 = O[base + t]       + X[base + t];
    float x1 = O[base + t + 256] + X[base + t + 256];

    red[t] = x0 + x1;
    __syncthreads();
    for (int o = 128; o > 0; o >>= 1) {
        if (t < o) red[t] += red[t + o];
        __syncthreads();
    }
    float mean = red[0] * (1.0f / DD);
    __syncthreads();

    float d0 = x0 - mean, d1 = x1 - mean;
    red[t] = d0 * d0 + d1 * d1;
    __syncthreads();
    for (int o = 128; o > 0; o >>= 1) {
        if (t < o) red[t] += red[t + o];
        __syncthreads();
    }
    float var = red[0] * (1.0f / DD);
    float inv = rsqrtf(var + 1e-5f);

    Y[base + t]       = d0 * inv * gamma[t]       + beta[t];
    Y[base + t + 256] = d1 * inv * gamma[t + 256] + beta[t + 256];
}

// ---------------- launch ----------------
extern "C" void kernel_launch(void* const* d_in, const int* in_sizes, int n_in,
                              void* d_out, int out_size)
{
    const float* Q     = (const float*)d_in[0];
    const float* K     = (const float*)d_in[1];
    const float* V     = (const float*)d_in[2];
    const void*  mask  = d_in[3];
    const float* WQ    = (const float*)d_in[4];
    const float* WK    = (const float*)d_in[5];
    const float* WV    = (const float*)d_in[6];
    const float* Wfc   = (const float*)d_in[7];
    const float* gamma = (const float*)d_in[8];
    const float* beta  = (const float*)d_in[9];

    float* y    = (float*)d_out;
    float* attn = y + (size_t)YSIZE;

    void *p;
    cudaGetSymbolAddress(&p, g_inhi);  bf16* inhi = (bf16*)p;
    cudaGetSymbolAddress(&p, g_inlo);  bf16* inlo = (bf16*)p;
    cudaGetSymbolAddress(&p, g_whi);   bf16* whi  = (bf16*)p;
    cudaGetSymbolAddress(&p, g_wlo);   bf16* wlo  = (bf16*)p;
    cudaGetSymbolAddress(&p, g_pjhi);  bf16* pjhi = (bf16*)p;
    cudaGetSymbolAddress(&p, g_pjlo);  bf16* pjlo = (bf16*)p;
    cudaGetSymbolAddress(&p, g_reshi); bf16* reshi= (bf16*)p;
    cudaGetSymbolAddress(&p, g_reslo); bf16* reslo= (bf16*)p;
    cudaGetSymbolAddress(&p, g_outp);  float* outp= (float*)p;

    cudaFuncSetAttribute(gemm_sp<true>,  cudaFuncAttributeMaxDynamicSharedMemorySize, GEMM_SMEM);
    cudaFuncSetAttribute(gemm_sp<false>, cudaFuncAttributeMaxDynamicSharedMemorySize, GEMM_SMEM);
    cudaFuncSetAttribute(attn_mma, cudaFuncAttributeMaxDynamicSharedMemorySize, ATTN_SMEM);

    detect_mask_kernel<<<1, 256>>>((const unsigned int*)mask, 65536);

    const size_t NE = (size_t)NTOK * DD;
    const int n4 = (int)(NE / 4);
    split_kernel<<<n4 / 256, 256>>>(Q, inhi,          inlo,          n4);
    split_kernel<<<n4 / 256, 256>>>(K, inhi + NE,     inlo + NE,     n4);
    split_kernel<<<n4 / 256, 256>>>(V, inhi + 2 * NE, inlo + 2 * NE, n4);
    const size_t WE = (size_t)DD * DD;
    const int w4 = (int)(WE / 4);
    split_kernel<<<w4 / 256, 256>>>(WQ,  whi,          wlo,          w4);
    split_kernel<<<w4 / 256, 256>>>(WK,  whi + WE,     wlo + WE,     w4);
    split_kernel<<<w4 / 256, 256>>>(WV,  whi + 2 * WE, wlo + 2 * WE, w4);
    split_kernel<<<w4 / 256, 256>>>(Wfc, whi + 3 * WE, wlo + 3 * WE, w4);

    dim3 gg(DD / 128, NTOK / 128);
    gemm_sp<true><<<gg, 256, GEMM_SMEM>>>(inhi,          inlo,          whi,          wlo,
                                          nullptr, pjhi,          pjlo,          NTOK, DD, DD);
    gemm_sp<true><<<gg, 256, GEMM_SMEM>>>(inhi + NE,     inlo + NE,     whi + WE,     wlo + WE,
                                          nullptr, pjhi + NE,     pjlo + NE,     NTOK, DD, DD);
    gemm_sp<true><<<gg, 256, GEMM_SMEM>>>(inhi + 2 * NE, inlo + 2 * NE, whi + 2 * WE, wlo + 2 * WE,
                                          nullptr, pjhi + 2 * NE, pjlo + 2 * NE, NTOK, DD, DD);

    attn_mma<<<BB * NNN * HH * 2, 256, ATTN_SMEM>>>(pjhi, pjlo, mask, attn, reshi, reslo);

    gemm_sp<false><<<gg, 256, GEMM_SMEM>>>(reshi, reslo, whi + 3 * WE, wlo + 3 * WE,
                                           outp, nullptr, nullptr, NTOK, DD, DD);

    ln_kernel<<<NTOK, 256>>>(outp, Q, gamma, beta, y);
}

// round 6
// speedup vs baseline: 2.9606x; 1.2489x over previous
#include <cuda_runtime.h>
#include <cuda_fp16.h>
#include <cstdint>

#define BB   16
#define NNN  32
#define SS   128
#define DD   512
#define HH   8
#define NTOK (BB*NNN*SS)          // 65536
#define YSIZE  (NTOK*DD)          // 33554432

// ---------------- scratch ----------------
__device__ __half g_inhi[3ull*NTOK*DD];   // input Q,K,V fp16 hi
__device__ __half g_inlo[3ull*NTOK*DD];   // input Q,K,V fp16 lo
__device__ __half g_wf[4ull*DD*DD];       // weights single fp16
__device__ __half g_qhi[(size_t)NTOK*DD]; // Q projection hi
__device__ __half g_qlo[(size_t)NTOK*DD]; // Q projection lo
__device__ __half g_kf[(size_t)NTOK*DD];  // K projection single
__device__ __half g_vf[(size_t)NTOK*DD];  // V projection single
__device__ __half g_reshi[(size_t)NTOK*DD];
__device__ __half g_reslo[(size_t)NTOK*DD];
__device__ float  g_outp[(size_t)NTOK*DD];
__device__ int    g_mask_kind;

// ---------------- mask dtype detection ----------------
__global__ void detect_mask_kernel(const unsigned int* __restrict__ mw, int nwords) {
    __shared__ int s_not01, s_isfloat;
    if (threadIdx.x == 0) { s_not01 = 0; s_isfloat = 0; }
    __syncthreads();
    for (int i = threadIdx.x; i < nwords; i += blockDim.x) {
        unsigned v = mw[i];
        if (v == 0x3f800000u) s_isfloat = 1;
        else if (v > 1u) s_not01 = 1;
    }
    __syncthreads();
    if (threadIdx.x == 0) g_mask_kind = s_not01 ? 2 : (s_isfloat ? 1 : 0);
}

// ---------------- helpers ----------------
__device__ __forceinline__ unsigned pack_f16(float lo, float hi) {
    __half2 h = __floats2half2_rn(lo, hi);     // low half = lo
    return *(unsigned*)&h;
}
__device__ __forceinline__ float f16lo(unsigned u) { return __low2float(*(__half2*)&u); }
__device__ __forceinline__ float f16hi(unsigned u) { return __high2float(*(__half2*)&u); }

__device__ __forceinline__ void mma16816(float c[4],
    unsigned a0, unsigned a1, unsigned a2, unsigned a3, unsigned b0, unsigned b1)
{
    asm volatile(
        "mma.sync.aligned.m16n8k16.row.col.f32.f16.f16.f32 "
        "{%0,%1,%2,%3}, {%4,%5,%6,%7}, {%8,%9}, {%0,%1,%2,%3};"
        : "+f"(c[0]), "+f"(c[1]), "+f"(c[2]), "+f"(c[3])
        : "r"(a0), "r"(a1), "r"(a2), "r"(a3), "r"(b0), "r"(b1));
}
__device__ __forceinline__ void cpa16(uint32_t s, const void* g) {
    asm volatile("cp.async.cg.shared.global [%0], [%1], 16;" :: "r"(s), "l"(g));
}
__device__ __forceinline__ void ldsm4(unsigned& r0, unsigned& r1, unsigned& r2, unsigned& r3, uint32_t a) {
    asm volatile("ldmatrix.sync.aligned.m8n8.x4.shared.b16 {%0,%1,%2,%3}, [%4];"
        : "=r"(r0), "=r"(r1), "=r"(r2), "=r"(r3) : "r"(a));
}
__device__ __forceinline__ void ldsm4t(unsigned& r0, unsigned& r1, unsigned& r2, unsigned& r3, uint32_t a) {
    asm volatile("ldmatrix.sync.aligned.m8n8.x4.trans.shared.b16 {%0,%1,%2,%3}, [%4];"
        : "=r"(r0), "=r"(r1), "=r"(r2), "=r"(r3) : "r"(a));
}

// ---------------- split fp32 -> fp16 hi/lo ----------------
__global__ __launch_bounds__(256) void split_kernel(
    const float* __restrict__ src, __half* __restrict__ hi, __half* __restrict__ lo, int n4)
{
    int i = blockIdx.x * 256 + threadIdx.x;
    if (i >= n4) return;
    float4 v = ((const float4*)src)[i];
    unsigned h01 = pack_f16(v.x, v.y), h23 = pack_f16(v.z, v.w);
    unsigned l01 = pack_f16(v.x - f16lo(h01), v.y - f16hi(h01));
    unsigned l23 = pack_f16(v.z - f16lo(h23), v.w - f16hi(h23));
    ((uint2*)hi)[i] = make_uint2(h01, h23);
    ((uint2*)lo)[i] = make_uint2(l01, l23);
}

// ---------------- convert fp32 -> fp16 single ----------------
__global__ __launch_bounds__(256) void conv_kernel(
    const float* __restrict__ src, __half* __restrict__ dst, int n4)
{
    int i = blockIdx.x * 256 + threadIdx.x;
    if (i >= n4) return;
    float4 v = ((const float4*)src)[i];
    ((uint2*)dst)[i] = make_uint2(pack_f16(v.x, v.y), pack_f16(v.z, v.w));
}

// ---------------- GEMM: fp16x2 asym, cp.async double buffer, ldmatrix ----------------
// C[m][n] = sum_k A[m][k]*B[n][k];  A split (hi/lo), B single.
// Tiles: 128 rows x 32 f16 (64B rows), swizzle: ch ^= (row>>1)&3
// OUT: 0 = fp32 C, 1 = single f16 Chi, 2 = split f16 Chi/Clo
#define GEMM_SMEM 49152

template<int OUT>
__global__ __launch_bounds__(256, 2) void gemm_f16(
    const __half* __restrict__ Ahi, const __half* __restrict__ Alo,
    const __half* __restrict__ Bf,
    float* __restrict__ C, __half* __restrict__ Chi, __half* __restrict__ Clo,
    int M, int N, int K)
{
    extern __shared__ __half gsm[];
    const int tid = threadIdx.x;
    const int lane = tid & 31, wid = tid >> 5;
    const int wm = wid & 1, wn = wid >> 1;
    const int g = lane >> 2, q = lane & 3;
    const int lrow = (lane & 7) + ((lane >> 3) & 1) * 8;
    const int lch  = lane >> 4;
    const int n0 = blockIdx.x * 128, m0 = blockIdx.y * 128;
    uint32_t sb = (uint32_t)__cvta_generic_to_shared(gsm);

    auto issue = [&](int buf, int k0) {
#pragma unroll
        for (int j = 0; j < 6; j++) {
            int idx = tid + j * 256;
            int sub = j >> 1;               // 0: Ahi, 1: Alo, 2: B
            int t2 = idx & 511;
            int row = t2 >> 2, ch = t2 & 3;
            const __half* gp;
            if (sub == 0)      gp = Ahi + (size_t)(m0 + row) * K + k0 + ch * 8;
            else if (sub == 1) gp = Alo + (size_t)(m0 + row) * K + k0 + ch * 8;
            else               gp = Bf  + (size_t)(n0 + row) * K + k0 + ch * 8;
            uint32_t sa = sb + buf * 24576 + sub * 8192 + row * 64
                        + (((ch ^ ((row >> 1) & 3))) << 4);
            cpa16(sa, gp);
        }
        asm volatile("cp.async.commit_group;");
    };

    float acc[4][4][4] = {};
    const int nIter = K >> 5;
    issue(0, 0);
    issue(1, 32);

    for (int it = 0; it < nIter; it++) {
        if (it + 1 < nIter) asm volatile("cp.async.wait_group 1;");
        else                asm volatile("cp.async.wait_group 0;");
        __syncthreads();
        uint32_t bufb = sb + (it & 1) * 24576;
#pragma unroll
        for (int kb = 0; kb < 32; kb += 16) {
            int c0 = kb >> 3;
            unsigned ah[4][4], al[4][4];
#pragma unroll
            for (int i = 0; i < 4; i++) {
                int row = wm * 64 + i * 16 + lrow;
                uint32_t a = bufb + row * 64 + ((((c0 + lch) ^ ((row >> 1) & 3))) << 4);
                ldsm4(ah[i][0], ah[i][1], ah[i][2], ah[i][3], a);
                ldsm4(al[i][0], al[i][1], al[i][2], al[i][3], a + 8192);
            }
            unsigned bb[2][4];
#pragma unroll
            for (int p = 0; p < 2; p++) {
                int row = wn * 32 + p * 16 + lrow;
                uint32_t b = bufb + 16384 + row * 64 + ((((c0 + lch) ^ ((row >> 1) & 3))) << 4);
                ldsm4(bb[p][0], bb[p][1], bb[p][2], bb[p][3], b);
            }
#pragma unroll
            for (int j = 0; j < 4; j++) {
                int p = j >> 1, o = j & 1;
                unsigned b0 = bb[p][o], b1 = bb[p][o + 2];
#pragma unroll
                for (int i = 0; i < 4; i++) {
                    mma16816(acc[i][j], ah[i][0], ah[i][1], ah[i][2], ah[i][3], b0, b1);
                    mma16816(acc[i][j], al[i][0], al[i][1], al[i][2], al[i][3], b0, b1);
                }
            }
        }
        __syncthreads();
        if (it + 2 < nIter) issue(it & 1, (it + 2) << 5);
    }

#pragma unroll
    for (int i = 0; i < 4; i++) {
#pragma unroll
        for (int j = 0; j < 4; j++) {
            int row = m0 + wm * 64 + i * 16 + g;
            int col = n0 + wn * 32 + j * 8 + 2 * q;
            if (OUT == 0) {
                *(float2*)&C[(size_t)row * N + col]       = make_float2(acc[i][j][0], acc[i][j][1]);
                *(float2*)&C[(size_t)(row + 8) * N + col] = make_float2(acc[i][j][2], acc[i][j][3]);
            } else {
                unsigned h01 = pack_f16(acc[i][j][0], acc[i][j][1]);
                unsigned h23 = pack_f16(acc[i][j][2], acc[i][j][3]);
                *(unsigned*)&Chi[(size_t)row * N + col]       = h01;
                *(unsigned*)&Chi[(size_t)(row + 8) * N + col] = h23;
                if (OUT == 2) {
                    unsigned l01 = pack_f16(acc[i][j][0] - f16lo(h01), acc[i][j][1] - f16hi(h01));
                    unsigned l23 = pack_f16(acc[i][j][2] - f16lo(h23), acc[i][j][3] - f16hi(h23));
                    *(unsigned*)&Clo[(size_t)row * N + col]       = l01;
                    *(unsigned*)&Clo[(size_t)(row + 8) * N + col] = l23;
                }
            }
        }
    }
}

// ---------------- attention: 64 q-rows per CTA, 2 CTAs/SM ----------------
// smem: K single @0 (16KB), V single @16384 (16KB),
// Qh @32768 / Ql @40960 (8KB each) -- aliased by Ph/Pl after QK,
// P f32 @49152 (64 x 132).
#define SK_OFF 0
#define SV_OFF 16384
#define SQ_OFF 32768
#define SP_OFF 32768
#define PF_OFF 49152
#define ATTN_SMEM (PF_OFF + 64*132*4)

__global__ __launch_bounds__(256, 2) void attn_mma(
    const __half* __restrict__ qhi, const __half* __restrict__ qlo,
    const __half* __restrict__ kf, const __half* __restrict__ vf,
    const void* __restrict__ mask, float* __restrict__ attn_out,
    __half* __restrict__ res_hi, __half* __restrict__ res_lo)
{
    extern __shared__ char smc[];
    uint32_t sb = (uint32_t)__cvta_generic_to_shared(smc);
    float* P = (float*)(smc + PF_OFF);

    const int tid = threadIdx.x;
    const int lane = tid & 31, wid = tid >> 5;
    const int g = lane >> 2, q = lane & 3;
    const int lrow = (lane & 7) + ((lane >> 3) & 1) * 8;
    const int lch  = lane >> 4;
    const int qh = blockIdx.x & 1;
    const int h  = (blockIdx.x >> 1) & 7;
    const int bn = blockIdx.x >> 4;
    const int kind = g_mask_kind;

    const size_t base = (size_t)bn * 128 * DD + (size_t)h * 64;

    // ---- fill smem (swizzle ch^(row&7), 128B rows) ----
    {
#pragma unroll
        for (int t = 0; t < 2; t++) {
            int idx = tid + t * 256;
            int row = idx >> 3, ch = idx & 7;
            uint32_t sa = sb + SQ_OFF + row * 128 + (((ch ^ (row & 7))) << 4);
            size_t go = base + (size_t)(qh * 64 + row) * DD + ch * 8;
            cpa16(sa,        qhi + go);
            cpa16(sa + 8192, qlo + go);
        }
#pragma unroll
        for (int t = 0; t < 4; t++) {
            int idx = tid + t * 256;
            int row = idx >> 3, ch = idx & 7;
            uint32_t sw = (((ch ^ (row & 7))) << 4);
            size_t go = base + (size_t)row * DD + ch * 8;
            cpa16(sb + SK_OFF + row * 128 + sw, kf + go);
            cpa16(sb + SV_OFF + row * 128 + sw, vf + go);
        }
        asm volatile("cp.async.commit_group;");
        asm volatile("cp.async.wait_group 0;");
    }
    __syncthreads();

    const int wm = wid & 1, wn = wid >> 1;   // 2 x 4 warp grid, tile 32x32

    // ---- QK^T: A = Q split, B = K single ----
    {
        float acc[2][4][4] = {};
#pragma unroll
        for (int kb = 0; kb < 64; kb += 16) {
            int c0 = kb >> 3;
            unsigned ah[2][4], al[2][4];
#pragma unroll
            for (int i = 0; i < 2; i++) {
                int row = wm * 32 + i * 16 + lrow;
                uint32_t a = sb + SQ_OFF + row * 128 + ((((c0 + lch) ^ (row & 7))) << 4);
                ldsm4(ah[i][0], ah[i][1], ah[i][2], ah[i][3], a);
                ldsm4(al[i][0], al[i][1], al[i][2], al[i][3], a + 8192);
            }
            unsigned bk[2][4];
#pragma unroll
            for (int p = 0; p < 2; p++) {
                int row = wn * 32 + p * 16 + lrow;
                uint32_t b = sb + SK_OFF + row * 128 + ((((c0 + lch) ^ (row & 7))) << 4);
                ldsm4(bk[p][0], bk[p][1], bk[p][2], bk[p][3], b);
            }
#pragma unroll
            for (int j = 0; j < 4; j++) {
                int p = j >> 1, o = j & 1;
                unsigned b0 = bk[p][o], b1 = bk[p][o + 2];
#pragma unroll
                for (int i = 0; i < 2; i++) {
                    mma16816(acc[i][j], ah[i][0], ah[i][1], ah[i][2], ah[i][3], b0, b1);
                    mma16816(acc[i][j], al[i][0], al[i][1], al[i][2], al[i][3], b0, b1);
                }
            }
        }
#pragma unroll
        for (int i = 0; i < 2; i++)
#pragma unroll
            for (int j = 0; j < 4; j++) {
                int r = wm * 32 + i * 16 + g, c = wn * 32 + j * 8 + 2 * q;
                P[r * 132 + c]           = acc[i][j][0] * 0.125f;
                P[r * 132 + c + 1]       = acc[i][j][1] * 0.125f;
                P[(r + 8) * 132 + c]     = acc[i][j][2] * 0.125f;
                P[(r + 8) * 132 + c + 1] = acc[i][j][3] * 0.125f;
            }
    }
    __syncthreads();

    // ---- mask + softmax + attn_out (warp per row) ----
    {
        float* aout = attn_out + ((size_t)(bn * 8 + h)) * 16384 + (size_t)qh * 64 * 128;
#pragma unroll
        for (int rr = 0; rr < 8; rr++) {
            int rl = wid * 8 + rr;
            int gr = qh * 64 + rl;
            float4 v = *(float4*)&P[rl * 132 + 4 * lane];
            float m0, m1, m2, m3;
            if (kind == 2) {
                uchar4 mk = ((const uchar4*)((const unsigned char*)mask + (size_t)bn * 16384 + (size_t)gr * 128))[lane];
                m0 = mk.x ? 0.f : -1e9f; m1 = mk.y ? 0.f : -1e9f;
                m2 = mk.z ? 0.f : -1e9f; m3 = mk.w ? 0.f : -1e9f;
            } else if (kind == 1) {
                float4 mk = ((const float4*)((const float*)mask + (size_t)bn * 16384 + (size_t)gr * 128))[lane];
                m0 = mk.x != 0.f ? 0.f : -1e9f; m1 = mk.y != 0.f ? 0.f : -1e9f;
                m2 = mk.z != 0.f ? 0.f : -1e9f; m3 = mk.w != 0.f ? 0.f : -1e9f;
            } else {
                int4 mk = ((const int4*)((const int*)mask + (size_t)bn * 16384 + (size_t)gr * 128))[lane];
                m0 = mk.x ? 0.f : -1e9f; m1 = mk.y ? 0.f : -1e9f;
                m2 = mk.z ? 0.f : -1e9f; m3 = mk.w ? 0.f : -1e9f;
            }
            v.x += m0; v.y += m1; v.z += m2; v.w += m3;
            float mx = fmaxf(fmaxf(v.x, v.y), fmaxf(v.z, v.w));
#pragma unroll
            for (int o = 16; o; o >>= 1) mx = fmaxf(mx, __shfl_xor_sync(0xffffffffu, mx, o));
            v.x = __expf(v.x - mx); v.y = __expf(v.y - mx);
            v.z = __expf(v.z - mx); v.w = __expf(v.w - mx);
            float s = v.x + v.y + v.z + v.w;
#pragma unroll
            for (int o = 16; o; o >>= 1) s += __shfl_xor_sync(0xffffffffu, s, o);
            float inv = 1.0f / s;
            v.x *= inv; v.y *= inv; v.z *= inv; v.w *= inv;
            *(float4*)&P[rl * 132 + 4 * lane] = v;
            *(float4*)&aout[(size_t)rl * 128 + 4 * lane] = v;
        }
    }
    __syncthreads();

    // ---- P @ V in 2 k-chunks of 64 (P split aliases Q region) ----
    float acc_o[2][2][4] = {};
#pragma unroll
    for (int kc = 0; kc < 2; kc++) {
        for (int idx = tid; idx < 2048; idx += 256) {
            int row = idx >> 5, cp = (idx & 31) << 1;
            float p0 = P[row * 132 + kc * 64 + cp];
            float p1 = P[row * 132 + kc * 64 + cp + 1];
            unsigned hh = pack_f16(p0, p1);
            unsigned ll = pack_f16(p0 - f16lo(hh), p1 - f16hi(hh));
            uint32_t off = SP_OFF + row * 128 + ((((cp >> 3) ^ (row & 7))) << 4) + (cp & 7) * 2;
            *(unsigned*)(smc + off)        = hh;
            *(unsigned*)(smc + off + 8192) = ll;
        }
        __syncthreads();
#pragma unroll
        for (int kb = 0; kb < 64; kb += 16) {
            int c0 = kb >> 3;
            unsigned ah[2][4], al[2][4];
#pragma unroll
            for (int i = 0; i < 2; i++) {
                int row = wm * 32 + i * 16 + lrow;
                uint32_t a = sb + SP_OFF + row * 128 + ((((c0 + lch) ^ (row & 7))) << 4);
                ldsm4(ah[i][0], ah[i][1], ah[i][2], ah[i][3], a);
                ldsm4(al[i][0], al[i][1], al[i][2], al[i][3], a + 8192);
            }
            int vrow = kc * 64 + kb + lrow;
            uint32_t vb = sb + SV_OFF + vrow * 128 + ((((wn * 2 + lch) ^ (vrow & 7))) << 4);
            unsigned vv[4];
            ldsm4t(vv[0], vv[1], vv[2], vv[3], vb);
#pragma unroll
            for (int j = 0; j < 2; j++) {
                unsigned b0 = vv[2 * j], b1 = vv[2 * j + 1];
#pragma unroll
                for (int i = 0; i < 2; i++) {
                    mma16816(acc_o[i][j], ah[i][0], ah[i][1], ah[i][2], ah[i][3], b0, b1);
                    mma16816(acc_o[i][j], al[i][0], al[i][1], al[i][2], al[i][3], b0, b1);
                }
            }
        }
        __syncthreads();
    }

    // ---- epilogue: split res hi/lo (A operand of FC) ----
#pragma unroll
    for (int i = 0; i < 2; i++)
#pragma unroll
        for (int j = 0; j < 2; j++) {
            int row = wm * 32 + i * 16 + g;
            int col = h * 64 + wn * 16 + j * 8 + 2 * q;
            size_t o0 = ((size_t)(bn * 128 + qh * 64 + row)) * DD + col;
            size_t o1 = o0 + 8ull * DD;
            unsigned h01 = pack_f16(acc_o[i][j][0], acc_o[i][j][1]);
            unsigned l01 = pack_f16(acc_o[i][j][0] - f16lo(h01), acc_o[i][j][1] - f16hi(h01));
            unsigned h23 = pack_f16(acc_o[i][j][2], acc_o[i][j][3]);
            unsigned l23 = pack_f16(acc_o[i][j][2] - f16lo(h23), acc_o[i][j][3] - f16hi(h23));
            *(unsigned*)&res_hi[o0] = h01; *(unsigned*)&res_lo[o0] = l01;
            *(unsigned*)&res_hi[o1] = h23; *(unsigned*)&res_lo[o1] = l23;
        }
}

// ---------------- residual + LayerNorm ----------------
__global__ __launch_bounds__(256) void ln_kernel(
    const float* __restrict__ O, const float* __restrict__ X,
    const float* __restrict__ gamma, const float* __restrict__ beta,
    float* __restrict__ Y)
{
    __shared__ float red[256];
    size_t base = (size_t)blockIdx.x * DD;
    int t = threadIdx.x;
    float x0 = O[base + t]       + X[base + t];
    float x1 = O[base + t + 256] + X[base + t + 256];

    red[t] = x0 + x1;
    __syncthreads();
    for (int o = 128; o > 0; o >>= 1) {
        if (t < o) red[t] += red[t + o];
        __syncthreads();
    }
    float mean = red[0] * (1.0f / DD);
    __syncthreads();

    float d0 = x0 - mean, d1 = x1 - mean;
    red[t] = d0 * d0 + d1 * d1;
    __syncthreads();
    for (int o = 128; o > 0; o >>= 1) {
        if (t < o) red[t] += red[t + o];
        __syncthreads();
    }
    float var = red[0] * (1.0f / DD);
    float inv = rsqrtf(var + 1e-5f);

    Y[base + t]       = d0 * inv * gamma[t]       + beta[t];
    Y[base + t + 256] = d1 * inv * gamma[t + 256] + beta[t + 256];
}

// ---------------- launch ----------------
extern "C" void kernel_launch(void* const* d_in, const int* in_sizes, int n_in,
                              void* d_out, int out_size)
{
    const float* Q     = (const float*)d_in[0];
    const float* K     = (const float*)d_in[1];
    const float* V     = (const float*)d_in[2];
    const void*  mask  = d_in[3];
    const float* WQ    = (const float*)d_in[4];
    const float* WK    = (const float*)d_in[5];
    const float* WV    = (const float*)d_in[6];
    const float* Wfc   = (const float*)d_in[7];
    const float* gamma = (const float*)d_in[8];
    const float* beta  = (const float*)d_in[9];

    float* y    = (float*)d_out;
    float* attn = y + (size_t)YSIZE;

    void *p;
    cudaGetSymbolAddress(&p, g_inhi);  __half* inhi = (__half*)p;
    cudaGetSymbolAddress(&p, g_inlo);  __half* inlo = (__half*)p;
    cudaGetSymbolAddress(&p, g_wf);    __half* wf   = (__half*)p;
    cudaGetSymbolAddress(&p, g_qhi);   __half* qhi  = (__half*)p;
    cudaGetSymbolAddress(&p, g_qlo);   __half* qlo  = (__half*)p;
    cudaGetSymbolAddress(&p, g_kf);    __half* kf   = (__half*)p;
    cudaGetSymbolAddress(&p, g_vf);    __half* vfp  = (__half*)p;
    cudaGetSymbolAddress(&p, g_reshi); __half* reshi= (__half*)p;
    cudaGetSymbolAddress(&p, g_reslo); __half* reslo= (__half*)p;
    cudaGetSymbolAddress(&p, g_outp);  float* outp  = (float*)p;

    cudaFuncSetAttribute(gemm_f16<0>, cudaFuncAttributeMaxDynamicSharedMemorySize, GEMM_SMEM);
    cudaFuncSetAttribute(gemm_f16<1>, cudaFuncAttributeMaxDynamicSharedMemorySize, GEMM_SMEM);
    cudaFuncSetAttribute(gemm_f16<2>, cudaFuncAttributeMaxDynamicSharedMemorySize, GEMM_SMEM);
    cudaFuncSetAttribute(attn_mma, cudaFuncAttributeMaxDynamicSharedMemorySize, ATTN_SMEM);

    detect_mask_kernel<<<1, 256>>>((const unsigned int*)mask, 65536);

    const size_t NE = (size_t)NTOK * DD;
    const int n4 = (int)(NE / 4);
    split_kernel<<<n4 / 256, 256>>>(Q, inhi,          inlo,          n4);
    split_kernel<<<n4 / 256, 256>>>(K, inhi + NE,     inlo + NE,     n4);
    split_kernel<<<n4 / 256, 256>>>(V, inhi + 2 * NE, inlo + 2 * NE, n4);
    const size_t WE = (size_t)DD * DD;
    const int w4 = (int)(WE / 4);
    conv_kernel<<<w4 / 256, 256>>>(WQ,  wf,          w4);
    conv_kernel<<<w4 / 256, 256>>>(WK,  wf + WE,     w4);
    conv_kernel<<<w4 / 256, 256>>>(WV,  wf + 2 * WE, w4);
    conv_kernel<<<w4 / 256, 256>>>(Wfc, wf + 3 * WE, w4);

    dim3 gg(DD / 128, NTOK / 128);  // n-tile fastest -> A reuse in L2
    gemm_f16<2><<<gg, 256, GEMM_SMEM>>>(inhi,          inlo,          wf,
                                        nullptr, qhi, qlo, NTOK, DD, DD);
    gemm_f16<1><<<gg, 256, GEMM_SMEM>>>(inhi + NE,     inlo + NE,     wf + WE,
                                        nullptr, kf, nullptr, NTOK, DD, DD);
    gemm_f16<1><<<gg, 256, GEMM_SMEM>>>(inhi + 2 * NE, inlo + 2 * NE, wf + 2 * WE,
                                        nullptr, vfp, nullptr, NTOK, DD, DD);

    attn_mma<<<BB * NNN * HH * 2, 256, ATTN_SMEM>>>(qhi, qlo, kf, vfp, mask, attn, reshi, reslo);

    gemm_f16<0><<<gg, 256, GEMM_SMEM>>>(reshi, reslo, wf + 3 * WE,
                                        outp, nullptr, nullptr, NTOK, DD, DD);

    ln_kernel<<<NTOK, 256>>>(outp, Q, gamma, beta, y);
}

// round 7
// speedup vs baseline: 3.7859x; 1.2787x over previous
#include <cuda_runtime.h>
#include <cuda_fp16.h>
#include <cstdint>

#define BB   16
#define NNN  32
#define SS   128
#define DD   512
#define HH   8
#define NTOK (BB*NNN*SS)          // 65536
#define YSIZE  (NTOK*DD)          // 33554432

// ---------------- scratch ----------------
__device__ __half g_inf[3ull*NTOK*DD];    // inputs Q,K,V single f16
__device__ __half g_whi[4ull*DD*DD];      // weights hi
__device__ __half g_wlo[4ull*DD*DD];      // weights lo
__device__ __half g_qh[(size_t)NTOK*DD];  // Q proj hi
__device__ __half g_ql[(size_t)NTOK*DD];  // Q proj lo
__device__ __half g_kf[(size_t)NTOK*DD];  // K proj single
__device__ __half g_vf[(size_t)NTOK*DD];  // V proj single
__device__ __half g_resf[(size_t)NTOK*DD];// attn result single
__device__ __half g_outp[(size_t)NTOK*DD];// FC result f16
__device__ int    g_mask_kind;
__device__ int    g_flag_float, g_flag_not01;

// ---------------- mask dtype detection (parallel) ----------------
__global__ void detect_reset() { g_flag_float = 0; g_flag_not01 = 0; }
__global__ __launch_bounds__(256) void detect_scan(const uint4* __restrict__ mw) {
    int i = blockIdx.x * 256 + threadIdx.x;   // 16384 uint4 total
    uint4 w = mw[i];
    int isf = (w.x == 0x3f800000u) | (w.y == 0x3f800000u) | (w.z == 0x3f800000u) | (w.w == 0x3f800000u);
    int n01 = ((w.x > 1u) & (w.x != 0x3f800000u)) | ((w.y > 1u) & (w.y != 0x3f800000u))
            | ((w.z > 1u) & (w.z != 0x3f800000u)) | ((w.w > 1u) & (w.w != 0x3f800000u));
    int bf = __syncthreads_or(isf);
    int bn = __syncthreads_or(n01);
    if (threadIdx.x == 0) {
        if (bf) atomicOr(&g_flag_float, 1);
        if (bn) atomicOr(&g_flag_not01, 1);
    }
}
__global__ void detect_final() {
    g_mask_kind = g_flag_not01 ? 2 : (g_flag_float ? 1 : 0);
}

// ---------------- helpers ----------------
__device__ __forceinline__ unsigned pack_f16(float lo, float hi) {
    __half2 h = __floats2half2_rn(lo, hi);
    return *(unsigned*)&h;
}
__device__ __forceinline__ float f16lo(unsigned u) { return __low2float(*(__half2*)&u); }
__device__ __forceinline__ float f16hi(unsigned u) { return __high2float(*(__half2*)&u); }

__device__ __forceinline__ void mma16816(float c[4],
    unsigned a0, unsigned a1, unsigned a2, unsigned a3, unsigned b0, unsigned b1)
{
    asm volatile(
        "mma.sync.aligned.m16n8k16.row.col.f32.f16.f16.f32 "
        "{%0,%1,%2,%3}, {%4,%5,%6,%7}, {%8,%9}, {%0,%1,%2,%3};"
        : "+f"(c[0]), "+f"(c[1]), "+f"(c[2]), "+f"(c[3])
        : "r"(a0), "r"(a1), "r"(a2), "r"(a3), "r"(b0), "r"(b1));
}
__device__ __forceinline__ void cpa16(uint32_t s, const void* g) {
    asm volatile("cp.async.cg.shared.global [%0], [%1], 16;" :: "r"(s), "l"(g));
}
__device__ __forceinline__ void ldsm4(unsigned& r0, unsigned& r1, unsigned& r2, unsigned& r3, uint32_t a) {
    asm volatile("ldmatrix.sync.aligned.m8n8.x4.shared.b16 {%0,%1,%2,%3}, [%4];"
        : "=r"(r0), "=r"(r1), "=r"(r2), "=r"(r3) : "r"(a));
}
__device__ __forceinline__ void ldsm4t(unsigned& r0, unsigned& r1, unsigned& r2, unsigned& r3, uint32_t a) {
    asm volatile("ldmatrix.sync.aligned.m8n8.x4.trans.shared.b16 {%0,%1,%2,%3}, [%4];"
        : "=r"(r0), "=r"(r1), "=r"(r2), "=r"(r3) : "r"(a));
}

// ---------------- fp32 -> f16 single ----------------
__global__ __launch_bounds__(256) void conv_kernel(
    const float* __restrict__ src, __half* __restrict__ dst, int n4)
{
    int i = blockIdx.x * 256 + threadIdx.x;
    if (i >= n4) return;
    float4 v = ((const float4*)src)[i];
    ((uint2*)dst)[i] = make_uint2(pack_f16(v.x, v.y), pack_f16(v.z, v.w));
}

// ---------------- fp32 -> f16 hi/lo (weights) ----------------
__global__ __launch_bounds__(256) void split_kernel(
    const float* __restrict__ src, __half* __restrict__ hi, __half* __restrict__ lo, int n4)
{
    int i = blockIdx.x * 256 + threadIdx.x;
    if (i >= n4) return;
    float4 v = ((const float4*)src)[i];
    unsigned h01 = pack_f16(v.x, v.y), h23 = pack_f16(v.z, v.w);
    unsigned l01 = pack_f16(v.x - f16lo(h01), v.y - f16hi(h01));
    unsigned l23 = pack_f16(v.z - f16lo(h23), v.w - f16hi(h23));
    ((uint2*)hi)[i] = make_uint2(h01, h23);
    ((uint2*)lo)[i] = make_uint2(l01, l23);
}

// ---------------- GEMM: A single f16, B split (weights), cp.async 2-stage ----------------
// C[m][n] = sum_k A[m][k] * (Bhi[n][k]+Blo[n][k]).
// Planes: A @0, Bh @8192, Bl @16384; tile 128 rows x 32 f16 (64B rows), swizzle ch^((row>>1)&3)
// OUT: 1 = single f16 Chi, 2 = split f16 Chi/Clo
#define GEMM_SMEM 49152

template<int OUT>
__global__ __launch_bounds__(256, 2) void gemm_f16(
    const __half* __restrict__ Af,
    const __half* __restrict__ Bhi, const __half* __restrict__ Blo,
    __half* __restrict__ Chi, __half* __restrict__ Clo,
    int M, int N, int K)
{
    extern __shared__ __half gsm[];
    const int tid = threadIdx.x;
    const int lane = tid & 31, wid = tid >> 5;
    const int wm = wid & 1, wn = wid >> 1;
    const int g = lane >> 2, q = lane & 3;
    const int lrow = (lane & 7) + ((lane >> 3) & 1) * 8;
    const int lch  = lane >> 4;
    const int n0 = blockIdx.x * 128, m0 = blockIdx.y * 128;
    uint32_t sb = (uint32_t)__cvta_generic_to_shared(gsm);

    auto issue = [&](int buf, int k0) {
#pragma unroll
        for (int j = 0; j < 6; j++) {
            int idx = tid + j * 256;
            int sub = j >> 1;               // 0: A, 1: Bh, 2: Bl
            int t2 = idx & 511;
            int row = t2 >> 2, ch = t2 & 3;
            const __half* gp;
            if (sub == 0)      gp = Af  + (size_t)(m0 + row) * K + k0 + ch * 8;
            else if (sub == 1) gp = Bhi + (size_t)(n0 + row) * K + k0 + ch * 8;
            else               gp = Blo + (size_t)(n0 + row) * K + k0 + ch * 8;
            uint32_t sa = sb + buf * 24576 + sub * 8192 + row * 64
                        + (((ch ^ ((row >> 1) & 3))) << 4);
            cpa16(sa, gp);
        }
        asm volatile("cp.async.commit_group;");
    };

    float acc[4][4][4] = {};
    const int nIter = K >> 5;
    issue(0, 0);
    issue(1, 32);

    for (int it = 0; it < nIter; it++) {
        if (it + 1 < nIter) asm volatile("cp.async.wait_group 1;");
        else                asm volatile("cp.async.wait_group 0;");
        __syncthreads();
        uint32_t bufb = sb + (it & 1) * 24576;
#pragma unroll
        for (int kb = 0; kb < 32; kb += 16) {
            int c0 = kb >> 3;
            unsigned af[4][4];
#pragma unroll
            for (int i = 0; i < 4; i++) {
                int row = wm * 64 + i * 16 + lrow;
                uint32_t a = bufb + row * 64 + ((((c0 + lch) ^ ((row >> 1) & 3))) << 4);
                ldsm4(af[i][0], af[i][1], af[i][2], af[i][3], a);
            }
            unsigned bh[2][4], bl[2][4];
#pragma unroll
            for (int p = 0; p < 2; p++) {
                int row = wn * 32 + p * 16 + lrow;
                uint32_t b = bufb + 8192 + row * 64 + ((((c0 + lch) ^ ((row >> 1) & 3))) << 4);
                ldsm4(bh[p][0], bh[p][1], bh[p][2], bh[p][3], b);
                ldsm4(bl[p][0], bl[p][1], bl[p][2], bl[p][3], b + 8192);
            }
#pragma unroll
            for (int j = 0; j < 4; j++) {
                int p = j >> 1, o = j & 1;
                unsigned b0h = bh[p][o], b1h = bh[p][o + 2];
                unsigned b0l = bl[p][o], b1l = bl[p][o + 2];
#pragma unroll
                for (int i = 0; i < 4; i++) {
                    mma16816(acc[i][j], af[i][0], af[i][1], af[i][2], af[i][3], b0h, b1h);
                    mma16816(acc[i][j], af[i][0], af[i][1], af[i][2], af[i][3], b0l, b1l);
                }
            }
        }
        __syncthreads();
        if (it + 2 < nIter) issue(it & 1, (it + 2) << 5);
    }

#pragma unroll
    for (int i = 0; i < 4; i++) {
#pragma unroll
        for (int j = 0; j < 4; j++) {
            int row = m0 + wm * 64 + i * 16 + g;
            int col = n0 + wn * 32 + j * 8 + 2 * q;
            unsigned h01 = pack_f16(acc[i][j][0], acc[i][j][1]);
            unsigned h23 = pack_f16(acc[i][j][2], acc[i][j][3]);
            *(unsigned*)&Chi[(size_t)row * N + col]       = h01;
            *(unsigned*)&Chi[(size_t)(row + 8) * N + col] = h23;
            if (OUT == 2) {
                unsigned l01 = pack_f16(acc[i][j][0] - f16lo(h01), acc[i][j][1] - f16hi(h01));
                unsigned l23 = pack_f16(acc[i][j][2] - f16lo(h23), acc[i][j][3] - f16hi(h23));
                *(unsigned*)&Clo[(size_t)row * N + col]       = l01;
                *(unsigned*)&Clo[(size_t)(row + 8) * N + col] = l23;
            }
        }
    }
}

// ---------------- attention: 128 q-rows/CTA, register softmax ----------------
// smem: K @0 (16KB), V @16384 (16KB), Qh @32768 (16KB), Ql @49152 (16KB);
// after QK the Q region (32KB) is reused as P single f16 (128 x 128, 256B rows);
// stageMax @65536 (2KB), stageSum @67584 (2KB).
#define AK_OFF  0
#define AV_OFF  16384
#define AQH_OFF 32768
#define AQL_OFF 49152
#define AP_OFF  32768
#define ASTM_OFF 65536
#define ASTS_OFF 67584
#define ATTN_SMEM 69632

__global__ __launch_bounds__(256, 2) void attn_mma(
    const __half* __restrict__ qhi, const __half* __restrict__ qlo,
    const __half* __restrict__ kf, const __half* __restrict__ vf,
    const void* __restrict__ mask, float* __restrict__ attn_out,
    __half* __restrict__ resf)
{
    extern __shared__ char smc[];
    uint32_t sb = (uint32_t)__cvta_generic_to_shared(smc);
    float* stM = (float*)(smc + ASTM_OFF);
    float* stS = (float*)(smc + ASTS_OFF);

    const int tid = threadIdx.x;
    const int lane = tid & 31, wid = tid >> 5;
    const int g = lane >> 2, q = lane & 3;
    const int lrow = (lane & 7) + ((lane >> 3) & 1) * 8;
    const int lch  = lane >> 4;
    const int h  = blockIdx.x & 7;
    const int bn = blockIdx.x >> 3;
    const int kind = g_mask_kind;

    const size_t base = (size_t)bn * 128 * DD + (size_t)h * 64;

    // ---- fill K, V, Qh, Ql (each 128 rows x 64 f16, 128B rows, swizzle ch^(row&7)) ----
    {
#pragma unroll
        for (int t = 0; t < 4; t++) {
            int idx = tid + t * 256;
            int row = idx >> 3, ch = idx & 7;
            uint32_t sw = row * 128 + (((ch ^ (row & 7))) << 4);
            size_t go = base + (size_t)row * DD + ch * 8;
            cpa16(sb + AK_OFF  + sw, kf  + go);
            cpa16(sb + AV_OFF  + sw, vf  + go);
            cpa16(sb + AQH_OFF + sw, qhi + go);
            cpa16(sb + AQL_OFF + sw, qlo + go);
        }
        asm volatile("cp.async.commit_group;");
        asm volatile("cp.async.wait_group 0;");
    }
    __syncthreads();

    const int wm = wid & 1, wn = wid >> 1;   // rows: wm*64..+63, cols: wn*32..+31

    // ---- QK^T: A = Q hi/lo, B = K single; acc[i][j][4], k=64 ----
    float acc[4][4][4] = {};
#pragma unroll
    for (int kb = 0; kb < 64; kb += 16) {
        int c0 = kb >> 3;
        unsigned ah[4][4], al[4][4];
#pragma unroll
        for (int i = 0; i < 4; i++) {
            int row = wm * 64 + i * 16 + lrow;
            uint32_t a = sb + AQH_OFF + row * 128 + ((((c0 + lch) ^ (row & 7))) << 4);
            ldsm4(ah[i][0], ah[i][1], ah[i][2], ah[i][3], a);
            ldsm4(al[i][0], al[i][1], al[i][2], al[i][3], a + 16384);
        }
        unsigned bk[2][4];
#pragma unroll
        for (int p = 0; p < 2; p++) {
            int row = wn * 32 + p * 16 + lrow;
            uint32_t b = sb + AK_OFF + row * 128 + ((((c0 + lch) ^ (row & 7))) << 4);
            ldsm4(bk[p][0], bk[p][1], bk[p][2], bk[p][3], b);
        }
#pragma unroll
        for (int j = 0; j < 4; j++) {
            int p = j >> 1, o = j & 1;
            unsigned b0 = bk[p][o], b1 = bk[p][o + 2];
#pragma unroll
            for (int i = 0; i < 4; i++) {
                mma16816(acc[i][j], ah[i][0], ah[i][1], ah[i][2], ah[i][3], b0, b1);
                mma16816(acc[i][j], al[i][0], al[i][1], al[i][2], al[i][3], b0, b1);
            }
        }
    }

    // ---- mask + scale in registers ----
#pragma unroll
    for (int i = 0; i < 4; i++) {
#pragma unroll
        for (int hf = 0; hf < 2; hf++) {
            int r = wm * 64 + i * 16 + g + hf * 8;
            size_t mb = (size_t)bn * 16384 + (size_t)r * 128;
#pragma unroll
            for (int j = 0; j < 4; j++) {
                int c = wn * 32 + j * 8 + 2 * q;
                float m0, m1;
                if (kind == 2) {
                    uchar2 mk = *(const uchar2*)((const unsigned char*)mask + mb + c);
                    m0 = mk.x ? 0.f : -1e9f; m1 = mk.y ? 0.f : -1e9f;
                } else if (kind == 1) {
                    float2 mk = *(const float2*)((const float*)mask + mb + c);
                    m0 = (mk.x != 0.f) ? 0.f : -1e9f; m1 = (mk.y != 0.f) ? 0.f : -1e9f;
                } else {
                    int2 mk = *(const int2*)((const int*)mask + mb + c);
                    m0 = mk.x ? 0.f : -1e9f; m1 = mk.y ? 0.f : -1e9f;
                }
                acc[i][j][2 * hf]     = acc[i][j][2 * hf]     * 0.125f + m0;
                acc[i][j][2 * hf + 1] = acc[i][j][2 * hf + 1] * 0.125f + m1;
            }
        }
    }

    // ---- row max (quad shuffle + cross-warp stage) ----
    float mx[4][2];
#pragma unroll
    for (int i = 0; i < 4; i++)
#pragma unroll
        for (int hf = 0; hf < 2; hf++) {
            float m = -3.4e38f;
#pragma unroll
            for (int j = 0; j < 4; j++)
                m = fmaxf(m, fmaxf(acc[i][j][2 * hf], acc[i][j][2 * hf + 1]));
            m = fmaxf(m, __shfl_xor_sync(0xffffffffu, m, 1));
            m = fmaxf(m, __shfl_xor_sync(0xffffffffu, m, 2));
            mx[i][hf] = m;
            if (q == 0) stM[(wm * 64 + i * 16 + g + hf * 8) * 4 + wn] = m;
        }
    __syncthreads();

    float inv[4][2];
#pragma unroll
    for (int i = 0; i < 4; i++)
#pragma unroll
        for (int hf = 0; hf < 2; hf++) {
            int r = wm * 64 + i * 16 + g + hf * 8;
            float gm = fmaxf(fmaxf(stM[r * 4], stM[r * 4 + 1]), fmaxf(stM[r * 4 + 2], stM[r * 4 + 3]));
            float s = 0.f;
#pragma unroll
            for (int j = 0; j < 4; j++) {
                float e0 = __expf(acc[i][j][2 * hf]     - gm);
                float e1 = __expf(acc[i][j][2 * hf + 1] - gm);
                acc[i][j][2 * hf] = e0; acc[i][j][2 * hf + 1] = e1;
                s += e0 + e1;
            }
            s += __shfl_xor_sync(0xffffffffu, s, 1);
            s += __shfl_xor_sync(0xffffffffu, s, 2);
            mx[i][hf] = s;   // reuse as partial-sum holder
            if (q == 0) stS[r * 4 + wn] = s;
        }
    __syncthreads();

#pragma unroll
    for (int i = 0; i < 4; i++)
#pragma unroll
        for (int hf = 0; hf < 2; hf++) {
            int r = wm * 64 + i * 16 + g + hf * 8;
            inv[i][hf] = 1.0f / (stS[r * 4] + stS[r * 4 + 1] + stS[r * 4 + 2] + stS[r * 4 + 3]);
        }

    // ---- normalize + write attn_out + pack P single f16 into smem (256B rows) ----
    {
        float* aout = attn_out + ((size_t)(bn * 8 + h)) * 16384;
#pragma unroll
        for (int i = 0; i < 4; i++)
#pragma unroll
            for (int hf = 0; hf < 2; hf++) {
                int r = wm * 64 + i * 16 + g + hf * 8;
                float iv = inv[i][hf];
#pragma unroll
                for (int j = 0; j < 4; j++) {
                    int c = wn * 32 + j * 8 + 2 * q;
                    float p0 = acc[i][j][2 * hf] * iv;
                    float p1 = acc[i][j][2 * hf + 1] * iv;
                    *(float2*)&aout[(size_t)r * 128 + c] = make_float2(p0, p1);
                    uint32_t off = r * 256 + ((((c >> 3) ^ (r & 7))) << 4) + (c & 7) * 2;
                    *(unsigned*)(smc + AP_OFF + off) = pack_f16(p0, p1);
                }
            }
    }
    __syncthreads();

    // ---- P @ V: A = P single (k=128), B = V single ----
    float ao[4][2][4] = {};
#pragma unroll
    for (int kb = 0; kb < 8; kb++) {
        int c0 = kb * 2;
        unsigned ph[4][4];
#pragma unroll
        for (int i = 0; i < 4; i++) {
            int row = wm * 64 + i * 16 + lrow;
            uint32_t a = sb + AP_OFF + row * 256 + ((((c0 + lch) ^ (row & 7))) << 4);
            ldsm4(ph[i][0], ph[i][1], ph[i][2], ph[i][3], a);
        }
        int vrow = kb * 16 + lrow;
        uint32_t vb = sb + AV_OFF + vrow * 128 + ((((wn * 2 + lch) ^ (vrow & 7))) << 4);
        unsigned vv[4];
        ldsm4t(vv[0], vv[1], vv[2], vv[3], vb);
#pragma unroll
        for (int j = 0; j < 2; j++) {
            unsigned b0 = vv[2 * j], b1 = vv[2 * j + 1];
#pragma unroll
            for (int i = 0; i < 4; i++)
                mma16816(ao[i][j], ph[i][0], ph[i][1], ph[i][2], ph[i][3], b0, b1);
        }
    }

    // ---- epilogue: res single f16 ----
#pragma unroll
    for (int i = 0; i < 4; i++)
#pragma unroll
        for (int j = 0; j < 2; j++) {
            int row = wm * 64 + i * 16 + g;
            int col = h * 64 + wn * 16 + j * 8 + 2 * q;
            size_t o0 = ((size_t)(bn * 128 + row)) * DD + col;
            size_t o1 = o0 + 8ull * DD;
            *(unsigned*)&resf[o0] = pack_f16(ao[i][j][0], ao[i][j][1]);
            *(unsigned*)&resf[o1] = pack_f16(ao[i][j][2], ao[i][j][3]);
        }
}

// ---------------- residual + LayerNorm (f16 O) ----------------
__global__ __launch_bounds__(256) void ln_kernel(
    const __half* __restrict__ O, const float* __restrict__ X,
    const float* __restrict__ gamma, const float* __restrict__ beta,
    float* __restrict__ Y)
{
    __shared__ float red[256];
    size_t base = (size_t)blockIdx.x * DD;
    int t = threadIdx.x;
    float x0 = __half2float(O[base + t])       + X[base + t];
    float x1 = __half2float(O[base + t + 256]) + X[base + t + 256];

    red[t] = x0 + x1;
    __syncthreads();
    for (int o = 128; o > 0; o >>= 1) {
        if (t < o) red[t] += red[t + o];
        __syncthreads();
    }
    float mean = red[0] * (1.0f / DD);
    __syncthreads();

    float d0 = x0 - mean, d1 = x1 - mean;
    red[t] = d0 * d0 + d1 * d1;
    __syncthreads();
    for (int o = 128; o > 0; o >>= 1) {
        if (t < o) red[t] += red[t + o];
        __syncthreads();
    }
    float var = red[0] * (1.0f / DD);
    float inv = rsqrtf(var + 1e-5f);

    Y[base + t]       = d0 * inv * gamma[t]       + beta[t];
    Y[base + t + 256] = d1 * inv * gamma[t + 256] + beta[t + 256];
}

// ---------------- launch ----------------
extern "C" void kernel_launch(void* const* d_in, const int* in_sizes, int n_in,
                              void* d_out, int out_size)
{
    const float* Q     = (const float*)d_in[0];
    const float* K     = (const float*)d_in[1];
    const float* V     = (const float*)d_in[2];
    const void*  mask  = d_in[3];
    const float* WQ    = (const float*)d_in[4];
    const float* WK    = (const float*)d_in[5];
    const float* WV    = (const float*)d_in[6];
    const float* Wfc   = (const float*)d_in[7];
    const float* gamma = (const float*)d_in[8];
    const float* beta  = (const float*)d_in[9];

    float* y    = (float*)d_out;
    float* attn = y + (size_t)YSIZE;

    void *p;
    cudaGetSymbolAddress(&p, g_inf);  __half* inf  = (__half*)p;
    cudaGetSymbolAddress(&p, g_whi);  __half* whi  = (__half*)p;
    cudaGetSymbolAddress(&p, g_wlo);  __half* wlo  = (__half*)p;
    cudaGetSymbolAddress(&p, g_qh);   __half* qh   = (__half*)p;
    cudaGetSymbolAddress(&p, g_ql);   __half* ql   = (__half*)p;
    cudaGetSymbolAddress(&p, g_kf);   __half* kf   = (__half*)p;
    cudaGetSymbolAddress(&p, g_vf);   __half* vfp  = (__half*)p;
    cudaGetSymbolAddress(&p, g_resf); __half* resf = (__half*)p;
    cudaGetSymbolAddress(&p, g_outp); __half* outp = (__half*)p;

    cudaFuncSetAttribute(gemm_f16<1>, cudaFuncAttributeMaxDynamicSharedMemorySize, GEMM_SMEM);
    cudaFuncSetAttribute(gemm_f16<2>, cudaFuncAttributeMaxDynamicSharedMemorySize, GEMM_SMEM);
    cudaFuncSetAttribute(attn_mma, cudaFuncAttributeMaxDynamicSharedMemorySize, ATTN_SMEM);

    detect_reset<<<1, 1>>>();
    detect_scan<<<64, 256>>>((const uint4*)mask);
    detect_final<<<1, 1>>>();

    const size_t NE = (size_t)NTOK * DD;
    const int n4 = (int)(NE / 4);
    conv_kernel<<<n4 / 256, 256>>>(Q, inf,          n4);
    conv_kernel<<<n4 / 256, 256>>>(K, inf + NE,     n4);
    conv_kernel<<<n4 / 256, 256>>>(V, inf + 2 * NE, n4);
    const size_t WE = (size_t)DD * DD;
    const int w4 = (int)(WE / 4);
    split_kernel<<<w4 / 256, 256>>>(WQ,  whi,          wlo,          w4);
    split_kernel<<<w4 / 256, 256>>>(WK,  whi + WE,     wlo + WE,     w4);
    split_kernel<<<w4 / 256, 256>>>(WV,  whi + 2 * WE, wlo + 2 * WE, w4);
    split_kernel<<<w4 / 256, 256>>>(Wfc, whi + 3 * WE, wlo + 3 * WE, w4);

    dim3 gg(DD / 128, NTOK / 128);  // n-tile fastest -> A reuse in L2
    gemm_f16<2><<<gg, 256, GEMM_SMEM>>>(inf,          whi,          wlo,
                                        qh, ql, NTOK, DD, DD);
    gemm_f16<1><<<gg, 256, GEMM_SMEM>>>(inf + NE,     whi + WE,     wlo + WE,
                                        kf, nullptr, NTOK, DD, DD);
    gemm_f16<1><<<gg, 256, GEMM_SMEM>>>(inf + 2 * NE, whi + 2 * WE, wlo + 2 * WE,
                                        vfp, nullptr, NTOK, DD, DD);

    attn_mma<<<BB * NNN * HH, 256, ATTN_SMEM>>>(qh, ql, kf, vfp, mask, attn, resf);

    gemm_f16<1><<<gg, 256, GEMM_SMEM>>>(resf, whi + 3 * WE, wlo + 3 * WE,
                                        outp, nullptr, NTOK, DD, DD);

    ln_kernel<<<NTOK, 256>>>(outp, Q, gamma, beta, y);
}

// round 8
// speedup vs baseline: 4.0991x; 1.0827x over previous
#include <cuda_runtime.h>
#include <cuda_fp16.h>
#include <cstdint>

#define BB   16
#define NNN  32
#define SS   128
#define DD   512
#define HH   8
#define NTOK (BB*NNN*SS)          // 65536
#define YSIZE  (NTOK*DD)          // 33554432

// ---------------- scratch ----------------
__device__ __half g_inf[3ull*NTOK*DD];    // inputs Q,K,V single f16
__device__ __half g_whi[4ull*DD*DD];      // weights hi
__device__ __half g_wlo[4ull*DD*DD];      // weights lo
__device__ __half g_qh[(size_t)NTOK*DD];  // Q proj hi
__device__ __half g_ql[(size_t)NTOK*DD];  // Q proj lo
__device__ __half g_kf[(size_t)NTOK*DD];  // K proj single
__device__ __half g_vf[(size_t)NTOK*DD];  // V proj single
__device__ __half g_resf[(size_t)NTOK*DD];// attn result single
__device__ __half g_outp[(size_t)NTOK*DD];// FC result f16
__device__ int    g_mask_kind;
__device__ int    g_flag_float, g_flag_not01;

// ---------------- mask dtype detection (parallel) ----------------
__global__ void detect_reset() { g_flag_float = 0; g_flag_not01 = 0; }
__global__ __launch_bounds__(256) void detect_scan(const uint4* __restrict__ mw) {
    int i = blockIdx.x * 256 + threadIdx.x;
    uint4 w = mw[i];
    int isf = (w.x == 0x3f800000u) | (w.y == 0x3f800000u) | (w.z == 0x3f800000u) | (w.w == 0x3f800000u);
    int n01 = ((w.x > 1u) & (w.x != 0x3f800000u)) | ((w.y > 1u) & (w.y != 0x3f800000u))
            | ((w.z > 1u) & (w.z != 0x3f800000u)) | ((w.w > 1u) & (w.w != 0x3f800000u));
    int bf = __syncthreads_or(isf);
    int bn = __syncthreads_or(n01);
    if (threadIdx.x == 0) {
        if (bf) atomicOr(&g_flag_float, 1);
        if (bn) atomicOr(&g_flag_not01, 1);
    }
}
__global__ void detect_final() {
    g_mask_kind = g_flag_not01 ? 2 : (g_flag_float ? 1 : 0);
}

// ---------------- helpers ----------------
__device__ __forceinline__ unsigned pack_f16(float lo, float hi) {
    __half2 h = __floats2half2_rn(lo, hi);
    return *(unsigned*)&h;
}
__device__ __forceinline__ float f16lo(unsigned u) { return __low2float(*(__half2*)&u); }
__device__ __forceinline__ float f16hi(unsigned u) { return __high2float(*(__half2*)&u); }

__device__ __forceinline__ void mma16816(float c[4],
    unsigned a0, unsigned a1, unsigned a2, unsigned a3, unsigned b0, unsigned b1)
{
    asm volatile(
        "mma.sync.aligned.m16n8k16.row.col.f32.f16.f16.f32 "
        "{%0,%1,%2,%3}, {%4,%5,%6,%7}, {%8,%9}, {%0,%1,%2,%3};"
        : "+f"(c[0]), "+f"(c[1]), "+f"(c[2]), "+f"(c[3])
        : "r"(a0), "r"(a1), "r"(a2), "r"(a3), "r"(b0), "r"(b1));
}
__device__ __forceinline__ void cpa16(uint32_t s, const void* g) {
    asm volatile("cp.async.cg.shared.global [%0], [%1], 16;" :: "r"(s), "l"(g));
}
__device__ __forceinline__ void ldsm4(unsigned& r0, unsigned& r1, unsigned& r2, unsigned& r3, uint32_t a) {
    asm volatile("ldmatrix.sync.aligned.m8n8.x4.shared.b16 {%0,%1,%2,%3}, [%4];"
        : "=r"(r0), "=r"(r1), "=r"(r2), "=r"(r3) : "r"(a));
}
__device__ __forceinline__ void ldsm4t(unsigned& r0, unsigned& r1, unsigned& r2, unsigned& r3, uint32_t a) {
    asm volatile("ldmatrix.sync.aligned.m8n8.x4.trans.shared.b16 {%0,%1,%2,%3}, [%4];"
        : "=r"(r0), "=r"(r1), "=r"(r2), "=r"(r3) : "r"(a));
}

// ---------------- fp32 -> f16 single ----------------
__global__ __launch_bounds__(256) void conv_kernel(
    const float* __restrict__ src, __half* __restrict__ dst, int n4)
{
    int i = blockIdx.x * 256 + threadIdx.x;
    if (i >= n4) return;
    float4 v = ((const float4*)src)[i];
    ((uint2*)dst)[i] = make_uint2(pack_f16(v.x, v.y), pack_f16(v.z, v.w));
}

// ---------------- fp32 -> f16 hi/lo (weights) ----------------
__global__ __launch_bounds__(256) void split_kernel(
    const float* __restrict__ src, __half* __restrict__ hi, __half* __restrict__ lo, int n4)
{
    int i = blockIdx.x * 256 + threadIdx.x;
    if (i >= n4) return;
    float4 v = ((const float4*)src)[i];
    unsigned h01 = pack_f16(v.x, v.y), h23 = pack_f16(v.z, v.w);
    unsigned l01 = pack_f16(v.x - f16lo(h01), v.y - f16hi(h01));
    unsigned l23 = pack_f16(v.z - f16lo(h23), v.w - f16hi(h23));
    ((uint2*)hi)[i] = make_uint2(h01, h23);
    ((uint2*)lo)[i] = make_uint2(l01, l23);
}

// ---------------- GEMM: A single f16, B split; 3-stage cp.async, 1 sync/iter ----------------
// C[m][n] = sum_k A[m][k] * (Bhi[n][k]+Blo[n][k]).
// Stage: A @0, Bh @8192, Bl @16384 (each 128 rows x 32 f16, 64B rows, swizzle ch^((row>>1)&3))
#define GSTG 24576
#define GEMM_SMEM (3*GSTG)

template<int OUT>   // 1 = single f16 out, 2 = split hi/lo out
__global__ __launch_bounds__(256, 2) void gemm_f16(
    const __half* __restrict__ Af,
    const __half* __restrict__ Bhi, const __half* __restrict__ Blo,
    __half* __restrict__ Chi, __half* __restrict__ Clo,
    int M, int N, int K)
{
    extern __shared__ __half gsm[];
    const int tid = threadIdx.x;
    const int lane = tid & 31, wid = tid >> 5;
    const int wm = wid & 1, wn = wid >> 1;
    const int g = lane >> 2, q = lane & 3;
    const int lrow = (lane & 7) + ((lane >> 3) & 1) * 8;
    const int lch  = lane >> 4;
    const int n0 = blockIdx.x * 128, m0 = blockIdx.y * 128;
    uint32_t sb = (uint32_t)__cvta_generic_to_shared(gsm);

    auto issue = [&](int grp) {
        int k0 = grp << 5;
        uint32_t stg = sb + (grp % 3) * GSTG;
#pragma unroll
        for (int j = 0; j < 6; j++) {
            int idx = tid + j * 256;
            int sub = j >> 1;               // 0: A, 1: Bh, 2: Bl
            int t2 = idx & 511;
            int row = t2 >> 2, ch = t2 & 3;
            const __half* gp;
            if (sub == 0)      gp = Af  + (size_t)(m0 + row) * K + k0 + ch * 8;
            else if (sub == 1) gp = Bhi + (size_t)(n0 + row) * K + k0 + ch * 8;
            else               gp = Blo + (size_t)(n0 + row) * K + k0 + ch * 8;
            uint32_t sa = stg + sub * 8192 + row * 64
                        + (((ch ^ ((row >> 1) & 3))) << 4);
            cpa16(sa, gp);
        }
        asm volatile("cp.async.commit_group;");
    };

    float acc[4][4][4] = {};
    const int nIter = K >> 5;    // 16
    issue(0); issue(1);

    for (int it = 0; it < nIter; it++) {
        if (it < nIter - 1) asm volatile("cp.async.wait_group 1;");
        else                asm volatile("cp.async.wait_group 0;");
        __syncthreads();
        uint32_t bufb = sb + (it % 3) * GSTG;
#pragma unroll
        for (int kb = 0; kb < 32; kb += 16) {
            int c0 = kb >> 3;
            unsigned af[4][4];
#pragma unroll
            for (int i = 0; i < 4; i++) {
                int row = wm * 64 + i * 16 + lrow;
                uint32_t a = bufb + row * 64 + ((((c0 + lch) ^ ((row >> 1) & 3))) << 4);
                ldsm4(af[i][0], af[i][1], af[i][2], af[i][3], a);
            }
            unsigned bh[2][4], bl[2][4];
#pragma unroll
            for (int p = 0; p < 2; p++) {
                int row = wn * 32 + p * 16 + lrow;
                uint32_t b = bufb + 8192 + row * 64 + ((((c0 + lch) ^ ((row >> 1) & 3))) << 4);
                ldsm4(bh[p][0], bh[p][1], bh[p][2], bh[p][3], b);
                ldsm4(bl[p][0], bl[p][1], bl[p][2], bl[p][3], b + 8192);
            }
#pragma unroll
            for (int j = 0; j < 4; j++) {
                int p = j >> 1, o = j & 1;
                unsigned b0h = bh[p][o], b1h = bh[p][o + 2];
                unsigned b0l = bl[p][o], b1l = bl[p][o + 2];
#pragma unroll
                for (int i = 0; i < 4; i++) {
                    mma16816(acc[i][j], af[i][0], af[i][1], af[i][2], af[i][3], b0h, b1h);
                    mma16816(acc[i][j], af[i][0], af[i][1], af[i][2], af[i][3], b0l, b1l);
                }
            }
        }
        if (it + 2 < nIter) issue(it + 2);
    }

#pragma unroll
    for (int i = 0; i < 4; i++) {
#pragma unroll
        for (int j = 0; j < 4; j++) {
            int row = m0 + wm * 64 + i * 16 + g;
            int col = n0 + wn * 32 + j * 8 + 2 * q;
            unsigned h01 = pack_f16(acc[i][j][0], acc[i][j][1]);
            unsigned h23 = pack_f16(acc[i][j][2], acc[i][j][3]);
            *(unsigned*)&Chi[(size_t)row * N + col]       = h01;
            *(unsigned*)&Chi[(size_t)(row + 8) * N + col] = h23;
            if (OUT == 2) {
                unsigned l01 = pack_f16(acc[i][j][0] - f16lo(h01), acc[i][j][1] - f16hi(h01));
                unsigned l23 = pack_f16(acc[i][j][2] - f16lo(h23), acc[i][j][3] - f16hi(h23));
                *(unsigned*)&Clo[(size_t)row * N + col]       = l01;
                *(unsigned*)&Clo[(size_t)(row + 8) * N + col] = l23;
            }
        }
    }
}

// ---------------- attention: 128 q-rows/CTA, register softmax ----------------
// smem: K @0, V @16384, Qh @32768, Ql @49152 (each 16KB);
// Q region reused post-QK as P single f16 (128 x 128, 256B rows);
// mask u8 @65536 (16KB); stageMax @81920 (2KB); stageSum @83968 (2KB).
#define AK_OFF  0
#define AV_OFF  16384
#define AQH_OFF 32768
#define AQL_OFF 49152
#define AP_OFF  32768
#define AM_OFF  65536
#define ASTM_OFF 81920
#define ASTS_OFF 83968
#define ATTN_SMEM 86016

__global__ __launch_bounds__(256, 2) void attn_mma(
    const __half* __restrict__ qhi, const __half* __restrict__ qlo,
    const __half* __restrict__ kf, const __half* __restrict__ vf,
    const void* __restrict__ mask, float* __restrict__ attn_out,
    __half* __restrict__ resf)
{
    extern __shared__ char smc[];
    uint32_t sb = (uint32_t)__cvta_generic_to_shared(smc);
    float* stM = (float*)(smc + ASTM_OFF);
    float* stS = (float*)(smc + ASTS_OFF);

    const int tid = threadIdx.x;
    const int lane = tid & 31, wid = tid >> 5;
    const int g = lane >> 2, q = lane & 3;
    const int lrow = (lane & 7) + ((lane >> 3) & 1) * 8;
    const int lch  = lane >> 4;
    const int h  = blockIdx.x & 7;
    const int bn = blockIdx.x >> 3;
    const int kind = g_mask_kind;

    const size_t base = (size_t)bn * 128 * DD + (size_t)h * 64;

    // ---- group 0: K, Qh, Ql ----
    {
#pragma unroll
        for (int t = 0; t < 4; t++) {
            int idx = tid + t * 256;
            int row = idx >> 3, ch = idx & 7;
            uint32_t sw = row * 128 + (((ch ^ (row & 7))) << 4);
            size_t go = base + (size_t)row * DD + ch * 8;
            cpa16(sb + AK_OFF  + sw, kf  + go);
            cpa16(sb + AQH_OFF + sw, qhi + go);
            cpa16(sb + AQL_OFF + sw, qlo + go);
        }
        asm volatile("cp.async.commit_group;");
    }
    // ---- group 1: V (+ mask if u8) ----
    {
#pragma unroll
        for (int t = 0; t < 4; t++) {
            int idx = tid + t * 256;
            int row = idx >> 3, ch = idx & 7;
            uint32_t sw = row * 128 + (((ch ^ (row & 7))) << 4);
            cpa16(sb + AV_OFF + sw, vf + base + (size_t)row * DD + ch * 8);
        }
        if (kind == 2) {
#pragma unroll
            for (int t = 0; t < 4; t++) {
                int idx = tid + t * 256;
                int row = idx >> 3, ch = idx & 7;
                cpa16(sb + AM_OFF + row * 128 + ch * 16,
                      (const unsigned char*)mask + (size_t)bn * 16384 + (size_t)row * 128 + ch * 16);
            }
        }
        asm volatile("cp.async.commit_group;");
    }
    asm volatile("cp.async.wait_group 1;");
    __syncthreads();

    const int wm = wid & 1, wn = wid >> 1;   // rows: wm*64..+63, cols: wn*32..+31

    // ---- QK^T: A = Q hi/lo, B = K single ----
    float acc[4][4][4] = {};
#pragma unroll
    for (int kb = 0; kb < 64; kb += 16) {
        int c0 = kb >> 3;
        unsigned ah[4][4], al[4][4];
#pragma unroll
        for (int i = 0; i < 4; i++) {
            int row = wm * 64 + i * 16 + lrow;
            uint32_t a = sb + AQH_OFF + row * 128 + ((((c0 + lch) ^ (row & 7))) << 4);
            ldsm4(ah[i][0], ah[i][1], ah[i][2], ah[i][3], a);
            ldsm4(al[i][0], al[i][1], al[i][2], al[i][3], a + 16384);
        }
        unsigned bk[2][4];
#pragma unroll
        for (int p = 0; p < 2; p++) {
            int row = wn * 32 + p * 16 + lrow;
            uint32_t b = sb + AK_OFF + row * 128 + ((((c0 + lch) ^ (row & 7))) << 4);
            ldsm4(bk[p][0], bk[p][1], bk[p][2], bk[p][3], b);
        }
#pragma unroll
        for (int j = 0; j < 4; j++) {
            int p = j >> 1, o = j & 1;
            unsigned b0 = bk[p][o], b1 = bk[p][o + 2];
#pragma unroll
            for (int i = 0; i < 4; i++) {
                mma16816(acc[i][j], ah[i][0], ah[i][1], ah[i][2], ah[i][3], b0, b1);
                mma16816(acc[i][j], al[i][0], al[i][1], al[i][2], al[i][3], b0, b1);
            }
        }
    }

    // V (+mask) arrival; sync makes cross-thread cp.async data visible
    asm volatile("cp.async.wait_group 0;");
    __syncthreads();

    // ---- mask + scale in registers ----
#pragma unroll
    for (int i = 0; i < 4; i++) {
#pragma unroll
        for (int hf = 0; hf < 2; hf++) {
            int r = wm * 64 + i * 16 + g + hf * 8;
#pragma unroll
            for (int j = 0; j < 4; j++) {
                int c = wn * 32 + j * 8 + 2 * q;
                float m0, m1;
                if (kind == 2) {
                    uchar2 mk = *(const uchar2*)(smc + AM_OFF + r * 128 + c);
                    m0 = mk.x ? 0.f : -1e9f; m1 = mk.y ? 0.f : -1e9f;
                } else if (kind == 1) {
                    float2 mk = *(const float2*)((const float*)mask + (size_t)bn * 16384 + (size_t)r * 128 + c);
                    m0 = (mk.x != 0.f) ? 0.f : -1e9f; m1 = (mk.y != 0.f) ? 0.f : -1e9f;
                } else {
                    int2 mk = *(const int2*)((const int*)mask + (size_t)bn * 16384 + (size_t)r * 128 + c);
                    m0 = mk.x ? 0.f : -1e9f; m1 = mk.y ? 0.f : -1e9f;
                }
                acc[i][j][2 * hf]     = acc[i][j][2 * hf]     * 0.125f + m0;
                acc[i][j][2 * hf + 1] = acc[i][j][2 * hf + 1] * 0.125f + m1;
            }
        }
    }

    // ---- row max (quad shuffle + cross-warp stage) ----
#pragma unroll
    for (int i = 0; i < 4; i++)
#pragma unroll
        for (int hf = 0; hf < 2; hf++) {
            float m = -3.4e38f;
#pragma unroll
            for (int j = 0; j < 4; j++)
                m = fmaxf(m, fmaxf(acc[i][j][2 * hf], acc[i][j][2 * hf + 1]));
            m = fmaxf(m, __shfl_xor_sync(0xffffffffu, m, 1));
            m = fmaxf(m, __shfl_xor_sync(0xffffffffu, m, 2));
            if (q == 0) stM[(wm * 64 + i * 16 + g + hf * 8) * 4 + wn] = m;
        }
    __syncthreads();

    float inv[4][2];
#pragma unroll
    for (int i = 0; i < 4; i++)
#pragma unroll
        for (int hf = 0; hf < 2; hf++) {
            int r = wm * 64 + i * 16 + g + hf * 8;
            float gm = fmaxf(fmaxf(stM[r * 4], stM[r * 4 + 1]), fmaxf(stM[r * 4 + 2], stM[r * 4 + 3]));
            float s = 0.f;
#pragma unroll
            for (int j = 0; j < 4; j++) {
                float e0 = __expf(acc[i][j][2 * hf]     - gm);
                float e1 = __expf(acc[i][j][2 * hf + 1] - gm);
                acc[i][j][2 * hf] = e0; acc[i][j][2 * hf + 1] = e1;
                s += e0 + e1;
            }
            s += __shfl_xor_sync(0xffffffffu, s, 1);
            s += __shfl_xor_sync(0xffffffffu, s, 2);
            if (q == 0) stS[r * 4 + wn] = s;
        }
    __syncthreads();

#pragma unroll
    for (int i = 0; i < 4; i++)
#pragma unroll
        for (int hf = 0; hf < 2; hf++) {
            int r = wm * 64 + i * 16 + g + hf * 8;
            inv[i][hf] = 1.0f / (stS[r * 4] + stS[r * 4 + 1] + stS[r * 4 + 2] + stS[r * 4 + 3]);
        }

    // ---- normalize + write attn_out + pack P single f16 into smem (256B rows) ----
    {
        float* aout = attn_out + ((size_t)(bn * 8 + h)) * 16384;
#pragma unroll
        for (int i = 0; i < 4; i++)
#pragma unroll
            for (int hf = 0; hf < 2; hf++) {
                int r = wm * 64 + i * 16 + g + hf * 8;
                float iv = inv[i][hf];
#pragma unroll
                for (int j = 0; j < 4; j++) {
                    int c = wn * 32 + j * 8 + 2 * q;
                    float p0 = acc[i][j][2 * hf] * iv;
                    float p1 = acc[i][j][2 * hf + 1] * iv;
                    *(float2*)&aout[(size_t)r * 128 + c] = make_float2(p0, p1);
                    uint32_t off = r * 256 + ((((c >> 3) ^ (r & 7))) << 4) + (c & 7) * 2;
                    *(unsigned*)(smc + AP_OFF + off) = pack_f16(p0, p1);
                }
            }
    }
    __syncthreads();

    // ---- P @ V: A = P single (k=128), B = V single ----
    float ao[4][2][4] = {};
#pragma unroll
    for (int kb = 0; kb < 8; kb++) {
        int c0 = kb * 2;
        unsigned ph[4][4];
#pragma unroll
        for (int i = 0; i < 4; i++) {
            int row = wm * 64 + i * 16 + lrow;
            uint32_t a = sb + AP_OFF + row * 256 + ((((c0 + lch) ^ (row & 7))) << 4);
            ldsm4(ph[i][0], ph[i][1], ph[i][2], ph[i][3], a);
        }
        int vrow = kb * 16 + lrow;
        uint32_t vb = sb + AV_OFF + vrow * 128 + ((((wn * 2 + lch) ^ (vrow & 7))) << 4);
        unsigned vv[4];
        ldsm4t(vv[0], vv[1], vv[2], vv[3], vb);
#pragma unroll
        for (int j = 0; j < 2; j++) {
            unsigned b0 = vv[2 * j], b1 = vv[2 * j + 1];
#pragma unroll
            for (int i = 0; i < 4; i++)
                mma16816(ao[i][j], ph[i][0], ph[i][1], ph[i][2], ph[i][3], b0, b1);
        }
    }

    // ---- epilogue: res single f16 ----
#pragma unroll
    for (int i = 0; i < 4; i++)
#pragma unroll
        for (int j = 0; j < 2; j++) {
            int row = wm * 64 + i * 16 + g;
            int col = h * 64 + wn * 16 + j * 8 + 2 * q;
            size_t o0 = ((size_t)(bn * 128 + row)) * DD + col;
            size_t o1 = o0 + 8ull * DD;
            *(unsigned*)&resf[o0] = pack_f16(ao[i][j][0], ao[i][j][1]);
            *(unsigned*)&resf[o1] = pack_f16(ao[i][j][2], ao[i][j][3]);
        }
}

// ---------------- residual + LayerNorm: warp per row, single pass ----------------
__global__ __launch_bounds__(256) void ln_kernel(
    const __half* __restrict__ O, const float* __restrict__ X,
    const float* __restrict__ gamma, const float* __restrict__ beta,
    float* __restrict__ Y)
{
    const int lane = threadIdx.x & 31, w = threadIdx.x >> 5;
    const size_t row = (size_t)blockIdx.x * 8 + w;
    const size_t base = row * DD;

    float x[16];
    float s = 0.f, s2 = 0.f;
#pragma unroll
    for (int c = 0; c < 4; c++) {
        int col = c * 128 + lane * 4;
        uint2 o2 = *(const uint2*)&O[base + col];
        float4 xf = *(const float4*)&X[base + col];
        float v0 = f16lo(o2.x) + xf.x;
        float v1 = f16hi(o2.x) + xf.y;
        float v2 = f16lo(o2.y) + xf.z;
        float v3 = f16hi(o2.y) + xf.w;
        x[c * 4 + 0] = v0; x[c * 4 + 1] = v1; x[c * 4 + 2] = v2; x[c * 4 + 3] = v3;
        s  += v0 + v1 + v2 + v3;
        s2 += v0 * v0 + v1 * v1 + v2 * v2 + v3 * v3;
    }
#pragma unroll
    for (int o = 16; o; o >>= 1) {
        s  += __shfl_xor_sync(0xffffffffu, s,  o);
        s2 += __shfl_xor_sync(0xffffffffu, s2, o);
    }
    float mean = s * (1.0f / DD);
    float var  = s2 * (1.0f / DD) - mean * mean;
    float inv  = rsqrtf(var + 1e-5f);

#pragma unroll
    for (int c = 0; c < 4; c++) {
        int col = c * 128 + lane * 4;
        float4 gm = *(const float4*)&gamma[col];
        float4 bt = *(const float4*)&beta[col];
        float4 yv;
        yv.x = (x[c * 4 + 0] - mean) * inv * gm.x + bt.x;
        yv.y = (x[c * 4 + 1] - mean) * inv * gm.y + bt.y;
        yv.z = (x[c * 4 + 2] - mean) * inv * gm.z + bt.z;
        yv.w = (x[c * 4 + 3] - mean) * inv * gm.w + bt.w;
        *(float4*)&Y[base + col] = yv;
    }
}

// ---------------- launch ----------------
extern "C" void kernel_launch(void* const* d_in, const int* in_sizes, int n_in,
                              void* d_out, int out_size)
{
    const float* Q     = (const float*)d_in[0];
    const float* K     = (const float*)d_in[1];
    const float* V     = (const float*)d_in[2];
    const void*  mask  = d_in[3];
    const float* WQ    = (const float*)d_in[4];
    const float* WK    = (const float*)d_in[5];
    const float* WV    = (const float*)d_in[6];
    const float* Wfc   = (const float*)d_in[7];
    const float* gamma = (const float*)d_in[8];
    const float* beta  = (const float*)d_in[9];

    float* y    = (float*)d_out;
    float* attn = y + (size_t)YSIZE;

    void *p;
    cudaGetSymbolAddress(&p, g_inf);  __half* inf  = (__half*)p;
    cudaGetSymbolAddress(&p, g_whi);  __half* whi  = (__half*)p;
    cudaGetSymbolAddress(&p, g_wlo);  __half* wlo  = (__half*)p;
    cudaGetSymbolAddress(&p, g_qh);   __half* qh   = (__half*)p;
    cudaGetSymbolAddress(&p, g_ql);   __half* ql   = (__half*)p;
    cudaGetSymbolAddress(&p, g_kf);   __half* kf   = (__half*)p;
    cudaGetSymbolAddress(&p, g_vf);   __half* vfp  = (__half*)p;
    cudaGetSymbolAddress(&p, g_resf); __half* resf = (__half*)p;
    cudaGetSymbolAddress(&p, g_outp); __half* outp = (__half*)p;

    cudaFuncSetAttribute(gemm_f16<1>, cudaFuncAttributeMaxDynamicSharedMemorySize, GEMM_SMEM);
    cudaFuncSetAttribute(gemm_f16<2>, cudaFuncAttributeMaxDynamicSharedMemorySize, GEMM_SMEM);
    cudaFuncSetAttribute(attn_mma, cudaFuncAttributeMaxDynamicSharedMemorySize, ATTN_SMEM);

    detect_reset<<<1, 1>>>();
    detect_scan<<<64, 256>>>((const uint4*)mask);
    detect_final<<<1, 1>>>();

    const size_t NE = (size_t)NTOK * DD;
    const int n4 = (int)(NE / 4);
    conv_kernel<<<n4 / 256, 256>>>(Q, inf,          n4);
    conv_kernel<<<n4 / 256, 256>>>(K, inf + NE,     n4);
    conv_kernel<<<n4 / 256, 256>>>(V, inf + 2 * NE, n4);
    const size_t WE = (size_t)DD * DD;
    const int w4 = (int)(WE / 4);
    split_kernel<<<w4 / 256, 256>>>(WQ,  whi,          wlo,          w4);
    split_kernel<<<w4 / 256, 256>>>(WK,  whi + WE,     wlo + WE,     w4);
    split_kernel<<<w4 / 256, 256>>>(WV,  whi + 2 * WE, wlo + 2 * WE, w4);
    split_kernel<<<w4 / 256, 256>>>(Wfc, whi + 3 * WE, wlo + 3 * WE, w4);

    dim3 gg(DD / 128, NTOK / 128);  // n-tile fastest -> A reuse in L2
    gemm_f16<2><<<gg, 256, GEMM_SMEM>>>(inf,          whi,          wlo,
                                        qh, ql, NTOK, DD, DD);
    gemm_f16<1><<<gg, 256, GEMM_SMEM>>>(inf + NE,     whi + WE,     wlo + WE,
                                        kf, nullptr, NTOK, DD, DD);
    gemm_f16<1><<<gg, 256, GEMM_SMEM>>>(inf + 2 * NE, whi + 2 * WE, wlo + 2 * WE,
                                        vfp, nullptr, NTOK, DD, DD);

    attn_mma<<<BB * NNN * HH, 256, ATTN_SMEM>>>(qh, ql, kf, vfp, mask, attn, resf);

    gemm_f16<1><<<gg, 256, GEMM_SMEM>>>(resf, whi + 3 * WE, wlo + 3 * WE,
                                        outp, nullptr, NTOK, DD, DD);

    ln_kernel<<<NTOK / 8, 256>>>(outp, Q, gamma, beta, y);
}

// round 9
// speedup vs baseline: 4.1898x; 1.0221x over previous
#include <cuda_runtime.h>
#include <cuda_fp16.h>
#include <cstdint>

#define BB   16
#define NNN  32
#define SS   128
#define DD   512
#define HH   8
#define NTOK (BB*NNN*SS)          // 65536
#define YSIZE  (NTOK*DD)          // 33554432

// ---------------- scratch ----------------
__device__ __half g_inf[3ull*NTOK*DD];    // inputs Q,K,V single f16
__device__ __half g_whi[4ull*DD*DD];      // weights hi
__device__ __half g_wlo[4ull*DD*DD];      // weights lo
__device__ __half g_qh[(size_t)NTOK*DD];  // Q proj hi
__device__ __half g_ql[(size_t)NTOK*DD];  // Q proj lo
__device__ __half g_kf[(size_t)NTOK*DD];  // K proj single
__device__ __half g_vf[(size_t)NTOK*DD];  // V proj single
__device__ __half g_resf[(size_t)NTOK*DD];// attn result single
__device__ __half g_outp[(size_t)NTOK*DD];// FC result f16
__device__ int    g_flag_float, g_flag_not01;

// ---------------- mask dtype detection ----------------
__global__ void detect_reset() { g_flag_float = 0; g_flag_not01 = 0; }
__global__ __launch_bounds__(256) void detect_scan(const uint4* __restrict__ mw) {
    int i = blockIdx.x * 256 + threadIdx.x;
    uint4 w = mw[i];
    int isf = (w.x == 0x3f800000u) | (w.y == 0x3f800000u) | (w.z == 0x3f800000u) | (w.w == 0x3f800000u);
    int n01 = ((w.x > 1u) & (w.x != 0x3f800000u)) | ((w.y > 1u) & (w.y != 0x3f800000u))
            | ((w.z > 1u) & (w.z != 0x3f800000u)) | ((w.w > 1u) & (w.w != 0x3f800000u));
    int bf = __syncthreads_or(isf);
    int bn = __syncthreads_or(n01);
    if (threadIdx.x == 0) {
        if (bf) atomicOr(&g_flag_float, 1);
        if (bn) atomicOr(&g_flag_not01, 1);
    }
}

// ---------------- helpers ----------------
__device__ __forceinline__ unsigned pack_f16(float lo, float hi) {
    __half2 h = __floats2half2_rn(lo, hi);
    return *(unsigned*)&h;
}
__device__ __forceinline__ float f16lo(unsigned u) { return __low2float(*(__half2*)&u); }
__device__ __forceinline__ float f16hi(unsigned u) { return __high2float(*(__half2*)&u); }

__device__ __forceinline__ void mma16816(float c[4],
    unsigned a0, unsigned a1, unsigned a2, unsigned a3, unsigned b0, unsigned b1)
{
    asm volatile(
        "mma.sync.aligned.m16n8k16.row.col.f32.f16.f16.f32 "
        "{%0,%1,%2,%3}, {%4,%5,%6,%7}, {%8,%9}, {%0,%1,%2,%3};"
        : "+f"(c[0]), "+f"(c[1]), "+f"(c[2]), "+f"(c[3])
        : "r"(a0), "r"(a1), "r"(a2), "r"(a3), "r"(b0), "r"(b1));
}
__device__ __forceinline__ void cpa16(uint32_t s, const void* g) {
    asm volatile("cp.async.cg.shared.global [%0], [%1], 16;" :: "r"(s), "l"(g));
}
__device__ __forceinline__ void ldsm4(unsigned& r0, unsigned& r1, unsigned& r2, unsigned& r3, uint32_t a) {
    asm volatile("ldmatrix.sync.aligned.m8n8.x4.shared.b16 {%0,%1,%2,%3}, [%4];"
        : "=r"(r0), "=r"(r1), "=r"(r2), "=r"(r3) : "r"(a));
}
__device__ __forceinline__ void ldsm4t(unsigned& r0, unsigned& r1, unsigned& r2, unsigned& r3, uint32_t a) {
    asm volatile("ldmatrix.sync.aligned.m8n8.x4.trans.shared.b16 {%0,%1,%2,%3}, [%4];"
        : "=r"(r0), "=r"(r1), "=r"(r2), "=r"(r3) : "r"(a));
}
__device__ __forceinline__ void stcs2(float* p, float a, float b) {
    asm volatile("st.global.cs.v2.f32 [%0], {%1,%2};" :: "l"(p), "f"(a), "f"(b) : "memory");
}

// ---------------- fp32 -> f16 single (3 inputs merged) ----------------
__global__ __launch_bounds__(256) void conv3_kernel(
    const float* __restrict__ s0, const float* __restrict__ s1, const float* __restrict__ s2,
    __half* __restrict__ dst, int n4)
{
    int b = blockIdx.x;
    int sel = b / (n4 / 256);
    int i = (b % (n4 / 256)) * 256 + threadIdx.x;
    const float* src = sel == 0 ? s0 : (sel == 1 ? s1 : s2);
    float4 v = ((const float4*)src)[i];
    ((uint2*)dst)[(size_t)sel * n4 + i] = make_uint2(pack_f16(v.x, v.y), pack_f16(v.z, v.w));
}

// ---------------- fp32 -> f16 hi/lo (4 weights merged) ----------------
__global__ __launch_bounds__(256) void split4_kernel(
    const float* __restrict__ s0, const float* __restrict__ s1,
    const float* __restrict__ s2, const float* __restrict__ s3,
    __half* __restrict__ hi, __half* __restrict__ lo, int n4)
{
    int b = blockIdx.x;
    int sel = b / (n4 / 256);
    int i = (b % (n4 / 256)) * 256 + threadIdx.x;
    const float* src = sel == 0 ? s0 : (sel == 1 ? s1 : (sel == 2 ? s2 : s3));
    float4 v = ((const float4*)src)[i];
    unsigned h01 = pack_f16(v.x, v.y), h23 = pack_f16(v.z, v.w);
    unsigned l01 = pack_f16(v.x - f16lo(h01), v.y - f16hi(h01));
    unsigned l23 = pack_f16(v.z - f16lo(h23), v.w - f16hi(h23));
    size_t o = (size_t)sel * n4 + i;
    ((uint2*)hi)[o] = make_uint2(h01, h23);
    ((uint2*)lo)[o] = make_uint2(l01, l23);
}

// ---------------- GEMM core (macro-free shared structure) ----------------
// Stage: A @0, Bh @8192, Bl @16384 (128 rows x 32 f16, 64B rows, swizzle ch^((row>>1)&3))
#define GSTG 24576
#define GEMM_SMEM (3*GSTG)
#define NE_C ((size_t)NTOK * DD)
#define WE_C ((size_t)DD * DD)

// merged QKV projection: grid (12, M/128); bx: px = bx>>2 (proj), n-tile = bx&3
__global__ __launch_bounds__(256, 2) void qkv_gemm(
    const __half* __restrict__ inf,
    const __half* __restrict__ whi, const __half* __restrict__ wlo,
    __half* __restrict__ qh, __half* __restrict__ ql,
    __half* __restrict__ kf, __half* __restrict__ vf)
{
    extern __shared__ __half gsm[];
    const int tid = threadIdx.x;
    const int lane = tid & 31, wid = tid >> 5;
    const int wm = wid & 1, wn = wid >> 1;
    const int g = lane >> 2, q = lane & 3;
    const int lrow = (lane & 7) + ((lane >> 3) & 1) * 8;
    const int lch  = lane >> 4;
    const int px = blockIdx.x >> 2;
    const int n0 = (blockIdx.x & 3) * 128, m0 = blockIdx.y * 128;
    const int K = DD, N = DD;
    uint32_t sb = (uint32_t)__cvta_generic_to_shared(gsm);

    const __half* Af  = inf + (size_t)px * NE_C;
    const __half* Bhi = whi + (size_t)px * WE_C;
    const __half* Blo = wlo + (size_t)px * WE_C;

    auto issue = [&](int grp) {
        int k0 = grp << 5;
        uint32_t stg = sb + (grp % 3) * GSTG;
#pragma unroll
        for (int j = 0; j < 6; j++) {
            int idx = tid + j * 256;
            int sub = j >> 1;
            int t2 = idx & 511;
            int row = t2 >> 2, ch = t2 & 3;
            const __half* gp;
            if (sub == 0)      gp = Af  + (size_t)(m0 + row) * K + k0 + ch * 8;
            else if (sub == 1) gp = Bhi + (size_t)(n0 + row) * K + k0 + ch * 8;
            else               gp = Blo + (size_t)(n0 + row) * K + k0 + ch * 8;
            cpa16(stg + sub * 8192 + row * 64 + (((ch ^ ((row >> 1) & 3))) << 4), gp);
        }
        asm volatile("cp.async.commit_group;");
    };

    float acc[4][4][4] = {};
    const int nIter = K >> 5;
    issue(0); issue(1);

    for (int it = 0; it < nIter; it++) {
        if (it < nIter - 1) asm volatile("cp.async.wait_group 1;");
        else                asm volatile("cp.async.wait_group 0;");
        __syncthreads();
        if (it + 2 < nIter) issue(it + 2);
        uint32_t bufb = sb + (it % 3) * GSTG;
#pragma unroll
        for (int kb = 0; kb < 32; kb += 16) {
            int c0 = kb >> 3;
            unsigned af[4][4];
#pragma unroll
            for (int i = 0; i < 4; i++) {
                int row = wm * 64 + i * 16 + lrow;
                uint32_t a = bufb + row * 64 + ((((c0 + lch) ^ ((row >> 1) & 3))) << 4);
                ldsm4(af[i][0], af[i][1], af[i][2], af[i][3], a);
            }
            unsigned bh[2][4], bl[2][4];
#pragma unroll
            for (int p = 0; p < 2; p++) {
                int row = wn * 32 + p * 16 + lrow;
                uint32_t b = bufb + 8192 + row * 64 + ((((c0 + lch) ^ ((row >> 1) & 3))) << 4);
                ldsm4(bh[p][0], bh[p][1], bh[p][2], bh[p][3], b);
                ldsm4(bl[p][0], bl[p][1], bl[p][2], bl[p][3], b + 8192);
            }
#pragma unroll
            for (int j = 0; j < 4; j++) {
                int p = j >> 1, o = j & 1;
                unsigned b0h = bh[p][o], b1h = bh[p][o + 2];
                unsigned b0l = bl[p][o], b1l = bl[p][o + 2];
#pragma unroll
                for (int i = 0; i < 4; i++) {
                    mma16816(acc[i][j], af[i][0], af[i][1], af[i][2], af[i][3], b0h, b1h);
                    mma16816(acc[i][j], af[i][0], af[i][1], af[i][2], af[i][3], b0l, b1l);
                }
            }
        }
    }

    __half* Chi = px == 0 ? qh : (px == 1 ? kf : vf);
#pragma unroll
    for (int i = 0; i < 4; i++) {
#pragma unroll
        for (int j = 0; j < 4; j++) {
            int row = m0 + wm * 64 + i * 16 + g;
            int col = n0 + wn * 32 + j * 8 + 2 * q;
            unsigned h01 = pack_f16(acc[i][j][0], acc[i][j][1]);
            unsigned h23 = pack_f16(acc[i][j][2], acc[i][j][3]);
            *(unsigned*)&Chi[(size_t)row * N + col]       = h01;
            *(unsigned*)&Chi[(size_t)(row + 8) * N + col] = h23;
            if (px == 0) {
                unsigned l01 = pack_f16(acc[i][j][0] - f16lo(h01), acc[i][j][1] - f16hi(h01));
                unsigned l23 = pack_f16(acc[i][j][2] - f16lo(h23), acc[i][j][3] - f16hi(h23));
                *(unsigned*)&ql[(size_t)row * N + col]       = l01;
                *(unsigned*)&ql[(size_t)(row + 8) * N + col] = l23;
            }
        }
    }
}

// FC GEMM: single f16 out
__global__ __launch_bounds__(256, 2) void fc_gemm(
    const __half* __restrict__ Af,
    const __half* __restrict__ Bhi, const __half* __restrict__ Blo,
    __half* __restrict__ Chi)
{
    extern __shared__ __half gsm[];
    const int tid = threadIdx.x;
    const int lane = tid & 31, wid = tid >> 5;
    const int wm = wid & 1, wn = wid >> 1;
    const int g = lane >> 2, q = lane & 3;
    const int lrow = (lane & 7) + ((lane >> 3) & 1) * 8;
    const int lch  = lane >> 4;
    const int n0 = blockIdx.x * 128, m0 = blockIdx.y * 128;
    const int K = DD, N = DD;
    uint32_t sb = (uint32_t)__cvta_generic_to_shared(gsm);

    auto issue = [&](int grp) {
        int k0 = grp << 5;
        uint32_t stg = sb + (grp % 3) * GSTG;
#pragma unroll
        for (int j = 0; j < 6; j++) {
            int idx = tid + j * 256;
            int sub = j >> 1;
            int t2 = idx & 511;
            int row = t2 >> 2, ch = t2 & 3;
            const __half* gp;
            if (sub == 0)      gp = Af  + (size_t)(m0 + row) * K + k0 + ch * 8;
            else if (sub == 1) gp = Bhi + (size_t)(n0 + row) * K + k0 + ch * 8;
            else               gp = Blo + (size_t)(n0 + row) * K + k0 + ch * 8;
            cpa16(stg + sub * 8192 + row * 64 + (((ch ^ ((row >> 1) & 3))) << 4), gp);
        }
        asm volatile("cp.async.commit_group;");
    };

    float acc[4][4][4] = {};
    const int nIter = K >> 5;
    issue(0); issue(1);

    for (int it = 0; it < nIter; it++) {
        if (it < nIter - 1) asm volatile("cp.async.wait_group 1;");
        else                asm volatile("cp.async.wait_group 0;");
        __syncthreads();
        if (it + 2 < nIter) issue(it + 2);
        uint32_t bufb = sb + (it % 3) * GSTG;
#pragma unroll
        for (int kb = 0; kb < 32; kb += 16) {
            int c0 = kb >> 3;
            unsigned af[4][4];
#pragma unroll
            for (int i = 0; i < 4; i++) {
                int row = wm * 64 + i * 16 + lrow;
                uint32_t a = bufb + row * 64 + ((((c0 + lch) ^ ((row >> 1) & 3))) << 4);
                ldsm4(af[i][0], af[i][1], af[i][2], af[i][3], a);
            }
            unsigned bh[2][4], bl[2][4];
#pragma unroll
            for (int p = 0; p < 2; p++) {
                int row = wn * 32 + p * 16 + lrow;
                uint32_t b = bufb + 8192 + row * 64 + ((((c0 + lch) ^ ((row >> 1) & 3))) << 4);
                ldsm4(bh[p][0], bh[p][1], bh[p][2], bh[p][3], b);
                ldsm4(bl[p][0], bl[p][1], bl[p][2], bl[p][3], b + 8192);
            }
#pragma unroll
            for (int j = 0; j < 4; j++) {
                int p = j >> 1, o = j & 1;
                unsigned b0h = bh[p][o], b1h = bh[p][o + 2];
                unsigned b0l = bl[p][o], b1l = bl[p][o + 2];
#pragma unroll
                for (int i = 0; i < 4; i++) {
                    mma16816(acc[i][j], af[i][0], af[i][1], af[i][2], af[i][3], b0h, b1h);
                    mma16816(acc[i][j], af[i][0], af[i][1], af[i][2], af[i][3], b0l, b1l);
                }
            }
        }
    }

#pragma unroll
    for (int i = 0; i < 4; i++) {
#pragma unroll
        for (int j = 0; j < 4; j++) {
            int row = m0 + wm * 64 + i * 16 + g;
            int col = n0 + wn * 32 + j * 8 + 2 * q;
            *(unsigned*)&Chi[(size_t)row * N + col]       = pack_f16(acc[i][j][0], acc[i][j][1]);
            *(unsigned*)&Chi[(size_t)(row + 8) * N + col] = pack_f16(acc[i][j][2], acc[i][j][3]);
        }
    }
}

// ---------------- attention: 128 q-rows/CTA, register softmax ----------------
#define AK_OFF  0
#define AV_OFF  16384
#define AQH_OFF 32768
#define AQL_OFF 49152
#define AP_OFF  32768
#define AM_OFF  65536
#define ASTM_OFF 81920
#define ASTS_OFF 83968
#define ATTN_SMEM 86016

__global__ __launch_bounds__(256, 2) void attn_mma(
    const __half* __restrict__ qhi, const __half* __restrict__ qlo,
    const __half* __restrict__ kf, const __half* __restrict__ vf,
    const void* __restrict__ mask, float* __restrict__ attn_out,
    __half* __restrict__ resf)
{
    extern __shared__ char smc[];
    uint32_t sb = (uint32_t)__cvta_generic_to_shared(smc);
    float* stM = (float*)(smc + ASTM_OFF);
    float* stS = (float*)(smc + ASTS_OFF);

    const int tid = threadIdx.x;
    const int lane = tid & 31, wid = tid >> 5;
    const int g = lane >> 2, q = lane & 3;
    const int lrow = (lane & 7) + ((lane >> 3) & 1) * 8;
    const int lch  = lane >> 4;
    const int h  = blockIdx.x & 7;
    const int bn = blockIdx.x >> 3;
    const int kind = g_flag_not01 ? 2 : (g_flag_float ? 1 : 0);

    const size_t base = (size_t)bn * 128 * DD + (size_t)h * 64;

    // group 0: K, Qh, Ql
    {
#pragma unroll
        for (int t = 0; t < 4; t++) {
            int idx = tid + t * 256;
            int row = idx >> 3, ch = idx & 7;
            uint32_t sw = row * 128 + (((ch ^ (row & 7))) << 4);
            size_t go = base + (size_t)row * DD + ch * 8;
            cpa16(sb + AK_OFF  + sw, kf  + go);
            cpa16(sb + AQH_OFF + sw, qhi + go);
            cpa16(sb + AQL_OFF + sw, qlo + go);
        }
        asm volatile("cp.async.commit_group;");
    }
    // group 1: V (+ mask if u8)
    {
#pragma unroll
        for (int t = 0; t < 4; t++) {
            int idx = tid + t * 256;
            int row = idx >> 3, ch = idx & 7;
            uint32_t sw = row * 128 + (((ch ^ (row & 7))) << 4);
            cpa16(sb + AV_OFF + sw, vf + base + (size_t)row * DD + ch * 8);
        }
        if (kind == 2) {
#pragma unroll
            for (int t = 0; t < 4; t++) {
                int idx = tid + t * 256;
                int row = idx >> 3, ch = idx & 7;
                cpa16(sb + AM_OFF + row * 128 + ch * 16,
                      (const unsigned char*)mask + (size_t)bn * 16384 + (size_t)row * 128 + ch * 16);
            }
        }
        asm volatile("cp.async.commit_group;");
    }
    asm volatile("cp.async.wait_group 1;");
    __syncthreads();

    const int wm = wid & 1, wn = wid >> 1;

    // QK^T
    float acc[4][4][4] = {};
#pragma unroll
    for (int kb = 0; kb < 64; kb += 16) {
        int c0 = kb >> 3;
        unsigned ah[4][4], al[4][4];
#pragma unroll
        for (int i = 0; i < 4; i++) {
            int row = wm * 64 + i * 16 + lrow;
            uint32_t a = sb + AQH_OFF + row * 128 + ((((c0 + lch) ^ (row & 7))) << 4);
            ldsm4(ah[i][0], ah[i][1], ah[i][2], ah[i][3], a);
            ldsm4(al[i][0], al[i][1], al[i][2], al[i][3], a + 16384);
        }
        unsigned bk[2][4];
#pragma unroll
        for (int p = 0; p < 2; p++) {
            int row = wn * 32 + p * 16 + lrow;
            uint32_t b = sb + AK_OFF + row * 128 + ((((c0 + lch) ^ (row & 7))) << 4);
            ldsm4(bk[p][0], bk[p][1], bk[p][2], bk[p][3], b);
        }
#pragma unroll
        for (int j = 0; j < 4; j++) {
            int p = j >> 1, o = j & 1;
            unsigned b0 = bk[p][o], b1 = bk[p][o + 2];
#pragma unroll
            for (int i = 0; i < 4; i++) {
                mma16816(acc[i][j], ah[i][0], ah[i][1], ah[i][2], ah[i][3], b0, b1);
                mma16816(acc[i][j], al[i][0], al[i][1], al[i][2], al[i][3], b0, b1);
            }
        }
    }

    asm volatile("cp.async.wait_group 0;");
    __syncthreads();

    // mask + scale
#pragma unroll
    for (int i = 0; i < 4; i++) {
#pragma unroll
        for (int hf = 0; hf < 2; hf++) {
            int r = wm * 64 + i * 16 + g + hf * 8;
#pragma unroll
            for (int j = 0; j < 4; j++) {
                int c = wn * 32 + j * 8 + 2 * q;
                float m0, m1;
                if (kind == 2) {
                    uchar2 mk = *(const uchar2*)(smc + AM_OFF + r * 128 + c);
                    m0 = mk.x ? 0.f : -1e9f; m1 = mk.y ? 0.f : -1e9f;
                } else if (kind == 1) {
                    float2 mk = *(const float2*)((const float*)mask + (size_t)bn * 16384 + (size_t)r * 128 + c);
                    m0 = (mk.x != 0.f) ? 0.f : -1e9f; m1 = (mk.y != 0.f) ? 0.f : -1e9f;
                } else {
                    int2 mk = *(const int2*)((const int*)mask + (size_t)bn * 16384 + (size_t)r * 128 + c);
                    m0 = mk.x ? 0.f : -1e9f; m1 = mk.y ? 0.f : -1e9f;
                }
                acc[i][j][2 * hf]     = acc[i][j][2 * hf]     * 0.125f + m0;
                acc[i][j][2 * hf + 1] = acc[i][j][2 * hf + 1] * 0.125f + m1;
            }
        }
    }

    // row max
#pragma unroll
    for (int i = 0; i < 4; i++)
#pragma unroll
        for (int hf = 0; hf < 2; hf++) {
            float m = -3.4e38f;
#pragma unroll
            for (int j = 0; j < 4; j++)
                m = fmaxf(m, fmaxf(acc[i][j][2 * hf], acc[i][j][2 * hf + 1]));
            m = fmaxf(m, __shfl_xor_sync(0xffffffffu, m, 1));
            m = fmaxf(m, __shfl_xor_sync(0xffffffffu, m, 2));
            if (q == 0) stM[(wm * 64 + i * 16 + g + hf * 8) * 4 + wn] = m;
        }
    __syncthreads();

    float inv[4][2];
#pragma unroll
    for (int i = 0; i < 4; i++)
#pragma unroll
        for (int hf = 0; hf < 2; hf++) {
            int r = wm * 64 + i * 16 + g + hf * 8;
            float gm = fmaxf(fmaxf(stM[r * 4], stM[r * 4 + 1]), fmaxf(stM[r * 4 + 2], stM[r * 4 + 3]));
            float s = 0.f;
#pragma unroll
            for (int j = 0; j < 4; j++) {
                float e0 = __expf(acc[i][j][2 * hf]     - gm);
                float e1 = __expf(acc[i][j][2 * hf + 1] - gm);
                acc[i][j][2 * hf] = e0; acc[i][j][2 * hf + 1] = e1;
                s += e0 + e1;
            }
            s += __shfl_xor_sync(0xffffffffu, s, 1);
            s += __shfl_xor_sync(0xffffffffu, s, 2);
            if (q == 0) stS[r * 4 + wn] = s;
        }
    __syncthreads();

#pragma unroll
    for (int i = 0; i < 4; i++)
#pragma unroll
        for (int hf = 0; hf < 2; hf++) {
            int r = wm * 64 + i * 16 + g + hf * 8;
            inv[i][hf] = 1.0f / (stS[r * 4] + stS[r * 4 + 1] + stS[r * 4 + 2] + stS[r * 4 + 3]);
        }

    // normalize + attn_out (streaming) + P f16 pack
    {
        float* aout = attn_out + ((size_t)(bn * 8 + h)) * 16384;
#pragma unroll
        for (int i = 0; i < 4; i++)
#pragma unroll
            for (int hf = 0; hf < 2; hf++) {
                int r = wm * 64 + i * 16 + g + hf * 8;
                float iv = inv[i][hf];
#pragma unroll
                for (int j = 0; j < 4; j++) {
                    int c = wn * 32 + j * 8 + 2 * q;
                    float p0 = acc[i][j][2 * hf] * iv;
                    float p1 = acc[i][j][2 * hf + 1] * iv;
                    stcs2(&aout[(size_t)r * 128 + c], p0, p1);
                    uint32_t off = r * 256 + ((((c >> 3) ^ (r & 7))) << 4) + (c & 7) * 2;
                    *(unsigned*)(smc + AP_OFF + off) = pack_f16(p0, p1);
                }
            }
    }
    __syncthreads();

    // P @ V
    float ao[4][2][4] = {};
#pragma unroll
    for (int kb = 0; kb < 8; kb++) {
        int c0 = kb * 2;
        unsigned ph[4][4];
#pragma unroll
        for (int i = 0; i < 4; i++) {
            int row = wm * 64 + i * 16 + lrow;
            uint32_t a = sb + AP_OFF + row * 256 + ((((c0 + lch) ^ (row & 7))) << 4);
            ldsm4(ph[i][0], ph[i][1], ph[i][2], ph[i][3], a);
        }
        int vrow = kb * 16 + lrow;
        uint32_t vb = sb + AV_OFF + vrow * 128 + ((((wn * 2 + lch) ^ (vrow & 7))) << 4);
        unsigned vv[4];
        ldsm4t(vv[0], vv[1], vv[2], vv[3], vb);
#pragma unroll
        for (int j = 0; j < 2; j++) {
            unsigned b0 = vv[2 * j], b1 = vv[2 * j + 1];
#pragma unroll
            for (int i = 0; i < 4; i++)
                mma16816(ao[i][j], ph[i][0], ph[i][1], ph[i][2], ph[i][3], b0, b1);
        }
    }

#pragma unroll
    for (int i = 0; i < 4; i++)
#pragma unroll
        for (int j = 0; j < 2; j++) {
            int row = wm * 64 + i * 16 + g;
            int col = h * 64 + wn * 16 + j * 8 + 2 * q;
            size_t o0 = ((size_t)(bn * 128 + row)) * DD + col;
            size_t o1 = o0 + 8ull * DD;
            *(unsigned*)&resf[o0] = pack_f16(ao[i][j][0], ao[i][j][1]);
            *(unsigned*)&resf[o1] = pack_f16(ao[i][j][2], ao[i][j][3]);
        }
}

// ---------------- residual + LayerNorm: warp per row ----------------
__global__ __launch_bounds__(256) void ln_kernel(
    const __half* __restrict__ O, const float* __restrict__ X,
    const float* __restrict__ gamma, const float* __restrict__ beta,
    float* __restrict__ Y)
{
    const int lane = threadIdx.x & 31, w = threadIdx.x >> 5;
    const size_t row = (size_t)blockIdx.x * 8 + w;
    const size_t base = row * DD;

    float x[16];
    float s = 0.f, s2 = 0.f;
#pragma unroll
    for (int c = 0; c < 4; c++) {
        int col = c * 128 + lane * 4;
        uint2 o2 = *(const uint2*)&O[base + col];
        float4 xf = *(const float4*)&X[base + col];
        float v0 = f16lo(o2.x) + xf.x;
        float v1 = f16hi(o2.x) + xf.y;
        float v2 = f16lo(o2.y) + xf.z;
        float v3 = f16hi(o2.y) + xf.w;
        x[c * 4 + 0] = v0; x[c * 4 + 1] = v1; x[c * 4 + 2] = v2; x[c * 4 + 3] = v3;
        s  += v0 + v1 + v2 + v3;
        s2 += v0 * v0 + v1 * v1 + v2 * v2 + v3 * v3;
    }
#pragma unroll
    for (int o = 16; o; o >>= 1) {
        s  += __shfl_xor_sync(0xffffffffu, s,  o);
        s2 += __shfl_xor_sync(0xffffffffu, s2, o);
    }
    float mean = s * (1.0f / DD);
    float var  = s2 * (1.0f / DD) - mean * mean;
    float inv  = rsqrtf(var + 1e-5f);

#pragma unroll
    for (int c = 0; c < 4; c++) {
        int col = c * 128 + lane * 4;
        float4 gm = *(const float4*)&gamma[col];
        float4 bt = *(const float4*)&beta[col];
        float4 yv;
        yv.x = (x[c * 4 + 0] - mean) * inv * gm.x + bt.x;
        yv.y = (x[c * 4 + 1] - mean) * inv * gm.y + bt.y;
        yv.z = (x[c * 4 + 2] - mean) * inv * gm.z + bt.z;
        yv.w = (x[c * 4 + 3] - mean) * inv * gm.w + bt.w;
        *(float4*)&Y[base + col] = yv;
    }
}

// ---------------- launch ----------------
extern "C" void kernel_launch(void* const* d_in, const int* in_sizes, int n_in,
                              void* d_out, int out_size)
{
    const float* Q     = (const float*)d_in[0];
    const float* K     = (const float*)d_in[1];
    const float* V     = (const float*)d_in[2];
    const void*  mask  = d_in[3];
    const float* WQ    = (const float*)d_in[4];
    const float* WK    = (const float*)d_in[5];
    const float* WV    = (const float*)d_in[6];
    const float* Wfc   = (const float*)d_in[7];
    const float* gamma = (const float*)d_in[8];
    const float* beta  = (const float*)d_in[9];

    float* y    = (float*)d_out;
    float* attn = y + (size_t)YSIZE;

    void *p;
    cudaGetSymbolAddress(&p, g_inf);  __half* inf  = (__half*)p;
    cudaGetSymbolAddress(&p, g_whi);  __half* whi  = (__half*)p;
    cudaGetSymbolAddress(&p, g_wlo);  __half* wlo  = (__half*)p;
    cudaGetSymbolAddress(&p, g_qh);   __half* qh   = (__half*)p;
    cudaGetSymbolAddress(&p, g_ql);   __half* ql   = (__half*)p;
    cudaGetSymbolAddress(&p, g_kf);   __half* kf   = (__half*)p;
    cudaGetSymbolAddress(&p, g_vf);   __half* vfp  = (__half*)p;
    cudaGetSymbolAddress(&p, g_resf); __half* resf = (__half*)p;
    cudaGetSymbolAddress(&p, g_outp); __half* outp = (__half*)p;

    cudaFuncSetAttribute(qkv_gemm, cudaFuncAttributeMaxDynamicSharedMemorySize, GEMM_SMEM);
    cudaFuncSetAttribute(fc_gemm,  cudaFuncAttributeMaxDynamicSharedMemorySize, GEMM_SMEM);
    cudaFuncSetAttribute(attn_mma, cudaFuncAttributeMaxDynamicSharedMemorySize, ATTN_SMEM);

    detect_reset<<<1, 1>>>();
    detect_scan<<<64, 256>>>((const uint4*)mask);

    const int n4 = (int)(NE_C / 4);
    conv3_kernel<<<3 * (n4 / 256), 256>>>(Q, K, V, inf, n4);
    const int w4 = (int)(WE_C / 4);
    split4_kernel<<<4 * (w4 / 256), 256>>>(WQ, WK, WV, Wfc, whi, wlo, w4);

    qkv_gemm<<<dim3(12, NTOK / 128), 256, GEMM_SMEM>>>(inf, whi, wlo, qh, ql, kf, vfp);

    attn_mma<<<BB * NNN * HH, 256, ATTN_SMEM>>>(qh, ql, kf, vfp, mask, attn, resf);

    fc_gemm<<<dim3(4, NTOK / 128), 256, GEMM_SMEM>>>(resf, whi + 3 * WE_C, wlo + 3 * WE_C, outp);

    ln_kernel<<<NTOK / 8, 256>>>(outp, Q, gamma, beta, y);
}